// round 9
// baseline (speedup 1.0000x reference)
#include <cuda_runtime.h>
#include <cuda_fp16.h>
#include <cstdint>

#define NB 64
#define NT 512
#define ND 512
#define NI 1024
#define NG 2048
#define RCTA 64            // CTAs per recurrence chain
#define UPC 8              // units per CTA

typedef unsigned long long ull;
typedef unsigned uint;

// ---------------- static device scratch ----------------
__device__ __align__(16) float g_xw1[(size_t)NB * NT * NG];
__device__ __align__(16) float g_xwf[(size_t)NB * NT * NG];
__device__ __align__(16) float g_xwb[(size_t)NB * NT * NG];
__device__ __align__(16) float g_h1 [(size_t)NB * NT * ND];   // [b][t][u] fp32
__device__ __align__(16) float g_hf [(size_t)NB * NT * ND];
__device__ __align__(16) float g_hb [(size_t)NB * NT * ND];
// fp16 hi/lo h for the recurrence, layout [t][b][kpair] (kpair = u/2, 256 per b)
__device__ __align__(16) uint g_h1h[(size_t)NT * NB * 256];
__device__ __align__(16) uint g_h1l[(size_t)NT * NB * 256];
__device__ __align__(16) uint g_hfh[(size_t)NT * NB * 256];
__device__ __align__(16) uint g_hfl[(size_t)NT * NB * 256];
__device__ __align__(16) uint g_hbh[(size_t)NT * NB * 256];
__device__ __align__(16) uint g_hbl[(size_t)NT * NB * 256];
__device__ __align__(16) float g_Wt1[(size_t)NG * NI];
__device__ __align__(16) float g_Wtf[(size_t)NG * ND];
__device__ __align__(16) float g_Wtb[(size_t)NG * ND];
// fp16 split GEMM operands
__device__ __align__(16) uint g_Ah [(size_t)NB * NT * NI / 2];
__device__ __align__(16) uint g_Al [(size_t)NB * NT * NI / 2];
__device__ __align__(16) uint g_Bh1[(size_t)NG * NI / 2];
__device__ __align__(16) uint g_Bl1[(size_t)NG * NI / 2];
__device__ __align__(16) uint g_Bhf[(size_t)NG * ND / 2];
__device__ __align__(16) uint g_Blf[(size_t)NG * ND / 2];
__device__ __align__(16) uint g_Bhb[(size_t)NG * ND / 2];
__device__ __align__(16) uint g_Blb[(size_t)NG * ND / 2];
__device__ unsigned g_bar1;
__device__ unsigned g_barf;
__device__ unsigned g_barb;

__device__ __forceinline__ float sigm(float z) { return 1.f / (1.f + __expf(-z)); }
__device__ __forceinline__ uint pack16(float a, float b) {
    __half2 h = __floats2half2_rn(a, b); return *(uint*)&h;
}
__device__ __forceinline__ float res16(float a) {
    return a - __half2float(__float2half_rn(a));
}
__device__ __forceinline__ uint32_t smem_u32(const void* p) {
    uint32_t a;
    asm("{ .reg .u64 t; cvta.to.shared.u64 t, %1; cvt.u32.u64 %0, t; }" : "=r"(a) : "l"(p));
    return a;
}
__device__ __forceinline__ void ldsm_x4(uint* r, uint32_t addr) {
    asm volatile("ldmatrix.sync.aligned.m8n8.x4.shared.b16 {%0,%1,%2,%3}, [%4];"
                 : "=r"(r[0]), "=r"(r[1]), "=r"(r[2]), "=r"(r[3]) : "r"(addr));
}
__device__ __forceinline__ void mma_f16(float* d, const uint* a, const uint* b) {
    asm volatile(
        "mma.sync.aligned.m16n8k16.row.col.f32.f16.f16.f32 "
        "{%0,%1,%2,%3}, {%4,%5,%6,%7}, {%8,%9}, {%0,%1,%2,%3};"
        : "+f"(d[0]), "+f"(d[1]), "+f"(d[2]), "+f"(d[3])
        : "r"(a[0]), "r"(a[1]), "r"(a[2]), "r"(a[3]), "r"(b[0]), "r"(b[1]));
}

// ---------------- grid-group spin barrier (monotonic counter) ----------------
__device__ __forceinline__ void grid_barrier(unsigned* bar, unsigned target) {
    __threadfence();
    __syncthreads();
    if (threadIdx.x == 0) {
        atomicAdd(bar, 1u);
        while (*((volatile unsigned*)bar) < target) { }
        __threadfence();
    }
    __syncthreads();
}

__global__ void reset_bars_kernel() { g_bar1 = 0u; g_barf = 0u; g_barb = 0u; }

// ================= tensor-core LSTM chain =================
// 64 CTAs per chain, 8 units each (u0 = cta*8). z[64b x 32g] = h[64b x 512k] @ Uslice.
// Warp (nt=gate 0..3, kh=k-half 0..1): B(U) frags resident in regs; A(h) frags
// via ldmatrix from staged SMEM. kh pairs reduced through zsm.
// SMEM (uints): Ah[2][64][132], Al[2][64][132] = 33792; then zs 2304 f, zsm 2304 f.
#define AROW 132
#define AREG (64 * AROW)          // 8448 uints per region
#define SMEM_R ((4 * AREG + 2 * 2304) * 4)   // 153600 B

__device__ __forceinline__ void lstm_chain(
    const float* __restrict__ U, const float* __restrict__ xw,
    float* __restrict__ hout, uint* __restrict__ h16h, uint* __restrict__ h16l,
    unsigned* bar, int dir, int cta)
{
    extern __shared__ uint su[];
    float* zs  = (float*)(su + 4 * AREG);
    float* zsm = zs + 2304;
    const uint32_t sb = smem_u32(su);

    const int tid = threadIdx.x;
    const int wid = tid >> 5, lane = tid & 31;
    const int lr = lane >> 2, lc = lane & 3;
    const int nt = wid & 3, kh = wid >> 2;
    const int u0 = cta * UPC;
    const int gb = tid & 63, gup = tid >> 6;

    // ---- resident B-fragments of U (hi/lo), one-time ----
    uint bh[32], bl[32];
    const int gcol = nt * ND + u0 + lr;
    {
#pragma unroll
        for (int ks = 0; ks < 16; ++ks) {
            int k0 = kh * 256 + ks * 16 + 2 * lc;
            float u00 = U[(size_t)(k0)     * NG + gcol];
            float u01 = U[(size_t)(k0 + 1) * NG + gcol];
            float u10 = U[(size_t)(k0 + 8) * NG + gcol];
            float u11 = U[(size_t)(k0 + 9) * NG + gcol];
            bh[2 * ks + 0] = pack16(u00, u01);
            bh[2 * ks + 1] = pack16(u10, u11);
            bl[2 * ks + 0] = pack16(res16(u00), res16(u01));
            bl[2 * ks + 1] = pack16(res16(u10), res16(u11));
        }
    }
    // per-thread ldmatrix row offset (uints): row lane&15, k-half by lane>>4
    const uint a_off = (uint)((lane & 15) * AROW + ((lane >> 4) << 2));
    const uint32_t ah_base = sb + ((kh ? AREG : 0) + a_off) * 4;
    const uint32_t al_base = sb + ((2 * AREG + (kh ? AREG : 0)) + a_off) * 4;

    float c0 = 0.f, c1 = 0.f;

    for (int t = 0; t < NT; ++t) {
        const int tt = (dir > 0) ? t : (NT - 1 - t);
        // prefetch xw gate inputs into zs (overlaps barrier spin)
#pragma unroll
        for (int j = 0; j < 2; ++j) {
            int f = tid * 2 + j;
            int b = f >> 3, gi = (f >> 1) & 3, half = f & 1;
            float4 xv = *(const float4*)&xw[((size_t)b * NT + tt) * NG + (size_t)gi * ND + u0 + half * 4];
            *(float4*)&zs[b * 36 + gi * 8 + half * 4] = xv;
        }

        float acc[4][4];
#pragma unroll
        for (int mt = 0; mt < 4; ++mt)
#pragma unroll
            for (int q = 0; q < 4; ++q) acc[mt][q] = 0.f;

        if (t > 0) {
            grid_barrier(bar, (unsigned)t * RCTA);
            const int tprev = tt - dir;
            // stage h16 hi/lo into SMEM A regions (coalesced)
            {
                const uint4* srch = (const uint4*)(h16h + (size_t)tprev * NB * 256);
                const uint4* srcl = (const uint4*)(h16l + (size_t)tprev * NB * 256);
#pragma unroll
                for (int j = 0; j < 16; ++j) {
                    int f4 = j * 256 + tid;
                    int b = f4 >> 6, q = f4 & 63;
                    int khh = q >> 5, kp = (q & 31) << 2;
                    uint4 vh = srch[b * 64 + q];
                    uint4 vl = srcl[b * 64 + q];
                    *(uint4*)&su[khh * AREG + b * AROW + kp] = vh;
                    *(uint4*)&su[2 * AREG + khh * AREG + b * AROW + kp] = vl;
                }
            }
            __syncthreads();
            // MMA mainloop: warp's k-half, all 4 m-tiles, its resident gate cols
#pragma unroll
            for (int ks = 0; ks < 16; ++ks) {
#pragma unroll
                for (int mt = 0; mt < 4; ++mt) {
                    uint ah[4], al[4];
                    uint32_t off = (uint32_t)((mt * 16 * AROW + ks * 8) * 4);
                    ldsm_x4(ah, ah_base + off);
                    ldsm_x4(al, al_base + off);
                    mma_f16(acc[mt], ah, &bh[2 * ks]);
                    mma_f16(acc[mt], al, &bh[2 * ks]);
                    mma_f16(acc[mt], ah, &bl[2 * ks]);
                }
            }
            // kh reduction through zsm
            if (kh == 1) {
#pragma unroll
                for (int mt = 0; mt < 4; ++mt)
#pragma unroll
                    for (int q = 0; q < 4; ++q) {
                        int m = mt * 16 + lr + (q >> 1) * 8;
                        int g = nt * 8 + 2 * lc + (q & 1);
                        zsm[m * 36 + g] = acc[mt][q];
                    }
            }
            __syncthreads();
            if (kh == 0) {
#pragma unroll
                for (int mt = 0; mt < 4; ++mt)
#pragma unroll
                    for (int q = 0; q < 4; ++q) {
                        int m = mt * 16 + lr + (q >> 1) * 8;
                        int g = nt * 8 + 2 * lc + (q & 1);
                        zsm[m * 36 + g] += acc[mt][q];
                    }
            }
            __syncthreads();
        } else {
            __syncthreads();
        }

        // ---- gate: thread handles batch gb, units u0 + gup*2, +1 ----
        {
            float hpair[2];
#pragma unroll
            for (int j = 0; j < 2; ++j) {
                int uu = gup * 2 + j;
                float zm0 = 0.f, zm1 = 0.f, zm2 = 0.f, zm3 = 0.f;
                if (t > 0) {
                    zm0 = zsm[gb * 36 + 0 * 8 + uu];
                    zm1 = zsm[gb * 36 + 1 * 8 + uu];
                    zm2 = zsm[gb * 36 + 2 * 8 + uu];
                    zm3 = zsm[gb * 36 + 3 * 8 + uu];
                }
                float zi = zs[gb * 36 + 0 * 8 + uu] + zm0;
                float zf = zs[gb * 36 + 1 * 8 + uu] + zm1;
                float zg = zs[gb * 36 + 2 * 8 + uu] + zm2;
                float zo = zs[gb * 36 + 3 * 8 + uu] + zm3;
                float& cc = j ? c1 : c0;
                cc = fmaf(sigm(zf), cc, sigm(zi) * fmaxf(zg, 0.f));
                hpair[j] = sigm(zo) * fmaxf(cc, 0.f);
            }
            // fp32 h (for GEMM/LN): float2, 32B sector per batch across gup
            *(float2*)&hout[((size_t)gb * NT + tt) * ND + u0 + gup * 2] =
                make_float2(hpair[0], hpair[1]);
            // fp16 hi/lo h for next-step staging
            size_t hidx = (size_t)tt * NB * 256 + gb * 256 + (u0 >> 1) + gup;
            h16h[hidx] = pack16(hpair[0], hpair[1]);
            h16l[hidx] = pack16(res16(hpair[0]), res16(hpair[1]));
        }
        __syncthreads();
    }
}

__global__ __launch_bounds__(256, 1) void lstm1_kernel(const float* __restrict__ U)
{
    lstm_chain(U, g_xw1, g_h1, g_h1h, g_h1l, &g_bar1, 1, blockIdx.x);
}

__global__ __launch_bounds__(256, 1) void lstmfb_kernel(
    const float* __restrict__ Uf, const float* __restrict__ Ub)
{
    if (blockIdx.x < RCTA)
        lstm_chain(Uf, g_xwf, g_hf, g_hfh, g_hfl, &g_barf, 1, blockIdx.x);
    else
        lstm_chain(Ub, g_xwb, g_hb, g_hbh, g_hbl, &g_barb, -1, blockIdx.x - RCTA);
}

// ---------------- fp16 split: v -> hi + lo (packed pairs) ----------------
__global__ __launch_bounds__(256) void split_fp16_kernel(
    const float* __restrict__ src, uint* __restrict__ hi, uint* __restrict__ lo, int n4)
{
    int i = blockIdx.x * 256 + threadIdx.x;
    if (i >= n4) return;
    float4 v = ((const float4*)src)[i];
    uint2 ho, lo2;
    ho.x = pack16(v.x, v.y); ho.y = pack16(v.z, v.w);
    lo2.x = pack16(res16(v.x), res16(v.y));
    lo2.y = pack16(res16(v.z), res16(v.w));
    ((uint2*)hi)[i] = ho;
    ((uint2*)lo)[i] = lo2;
}

// ================= fp16 mma GEMM (unchanged from R7 pass) =================
#define KST 12
#define GARRU (128 * KST)
#define GBUFU (4 * GARRU)
#define SMEM_GEMM (2 * GBUFU * 4)

__global__ __launch_bounds__(256, 1) void gemm_fp16_kernel(
    const uint* __restrict__ Ah, const uint* __restrict__ Al,
    const uint* __restrict__ Bh, const uint* __restrict__ Bl,
    const float* __restrict__ bias, float* __restrict__ C, int K2)
{
    extern __shared__ uint sgu[];
    const int tid = threadIdx.x;
    const int wid = tid >> 5, lane = tid & 31;
    const int lr = lane >> 2, lc = lane & 3;
    const int warp_m = wid & 3, warp_n = wid >> 2;
    const int n0 = blockIdx.x * 128, m0 = blockIdx.y * 128;

    const int row_s = tid >> 1, half = tid & 1;
    const size_t aoff = (size_t)(m0 + row_s) * K2 + half * 4;
    const size_t boff = (size_t)(n0 + row_s) * K2 + half * 4;
    const uint sidx = row_s * KST + half * 4;

    float acc[2][8][4];
#pragma unroll
    for (int mt = 0; mt < 2; ++mt)
#pragma unroll
        for (int nt = 0; nt < 8; ++nt)
#pragma unroll
            for (int q = 0; q < 4; ++q) acc[mt][nt][q] = 0.f;

    const int nc = K2 >> 3;
    uint4 rAh, rAl, rBh, rBl;
    rAh = *(const uint4*)&Ah[aoff];
    rAl = *(const uint4*)&Al[aoff];
    rBh = *(const uint4*)&Bh[boff];
    rBl = *(const uint4*)&Bl[boff];
    *(uint4*)&sgu[0 * GARRU + sidx] = rAh;
    *(uint4*)&sgu[1 * GARRU + sidx] = rAl;
    *(uint4*)&sgu[2 * GARRU + sidx] = rBh;
    *(uint4*)&sgu[3 * GARRU + sidx] = rBl;
    __syncthreads();

#pragma unroll 1
    for (int c = 0; c < nc; ++c) {
        const int buf = c & 1;
        if (c + 1 < nc) {
            rAh = *(const uint4*)&Ah[aoff + (c + 1) * 8];
            rAl = *(const uint4*)&Al[aoff + (c + 1) * 8];
            rBh = *(const uint4*)&Bh[boff + (c + 1) * 8];
            rBl = *(const uint4*)&Bl[boff + (c + 1) * 8];
        }
        const uint* sAh = sgu + buf * GBUFU + 0 * GARRU;
        const uint* sAl = sgu + buf * GBUFU + 1 * GARRU;
        const uint* sBh = sgu + buf * GBUFU + 2 * GARRU;
        const uint* sBl = sgu + buf * GBUFU + 3 * GARRU;

        uint ah[2][4], al[2][4];
#pragma unroll
        for (int mt = 0; mt < 2; ++mt) {
            int row = warp_m * 32 + mt * 16 + lr;
            ah[mt][0] = sAh[row * KST + lc];
            ah[mt][1] = sAh[(row + 8) * KST + lc];
            ah[mt][2] = sAh[row * KST + lc + 4];
            ah[mt][3] = sAh[(row + 8) * KST + lc + 4];
            al[mt][0] = sAl[row * KST + lc];
            al[mt][1] = sAl[(row + 8) * KST + lc];
            al[mt][2] = sAl[row * KST + lc + 4];
            al[mt][3] = sAl[(row + 8) * KST + lc + 4];
        }
        uint bh[8][2], bl[8][2];
#pragma unroll
        for (int nt = 0; nt < 8; ++nt) {
            int n = warp_n * 64 + nt * 8 + lr;
            bh[nt][0] = sBh[n * KST + lc];
            bh[nt][1] = sBh[n * KST + lc + 4];
            bl[nt][0] = sBl[n * KST + lc];
            bl[nt][1] = sBl[n * KST + lc + 4];
        }
#pragma unroll
        for (int mt = 0; mt < 2; ++mt)
#pragma unroll
            for (int nt = 0; nt < 8; ++nt) {
                mma_f16(acc[mt][nt], ah[mt], bh[nt]);
                mma_f16(acc[mt][nt], al[mt], bh[nt]);
                mma_f16(acc[mt][nt], ah[mt], bl[nt]);
            }

        if (c + 1 < nc) {
            const int nb = (c + 1) & 1;
            *(uint4*)&sgu[nb * GBUFU + 0 * GARRU + sidx] = rAh;
            *(uint4*)&sgu[nb * GBUFU + 1 * GARRU + sidx] = rAl;
            *(uint4*)&sgu[nb * GBUFU + 2 * GARRU + sidx] = rBh;
            *(uint4*)&sgu[nb * GBUFU + 3 * GARRU + sidx] = rBl;
        }
        __syncthreads();
    }

#pragma unroll
    for (int mt = 0; mt < 2; ++mt) {
        int row = m0 + warp_m * 32 + mt * 16 + lr;
#pragma unroll
        for (int nt = 0; nt < 8; ++nt) {
            int col = n0 + warp_n * 64 + nt * 8 + 2 * lc;
            float2 bv = *(const float2*)&bias[col];
            float2 o0 = make_float2(acc[mt][nt][0] + bv.x, acc[mt][nt][1] + bv.y);
            float2 o1 = make_float2(acc[mt][nt][2] + bv.x, acc[mt][nt][3] + bv.y);
            *(float2*)&C[(size_t)row * NG + col] = o0;
            *(float2*)&C[(size_t)(row + 8) * NG + col] = o1;
        }
    }
}

// ---------------- weight transpose ----------------
__global__ __launch_bounds__(256) void transpose_kernel(
    const float* __restrict__ W, float* __restrict__ Wt, int K, int N)
{
    __shared__ float t[32][33];
    const int tx = threadIdx.x & 31, ty = threadIdx.x >> 5;
    const int n0 = blockIdx.x << 5, k0 = blockIdx.y << 5;
#pragma unroll
    for (int i = 0; i < 32; i += 8)
        t[ty + i][tx] = W[(size_t)(k0 + ty + i) * N + n0 + tx];
    __syncthreads();
#pragma unroll
    for (int i = 0; i < 32; i += 8)
        Wt[(size_t)(n0 + ty + i) * K + k0 + tx] = t[tx][ty + i];
}

// ---------------- LayerNorm + residual ----------------
__global__ __launch_bounds__(256) void ln_kernel(
    const float* __restrict__ x, const float* __restrict__ gamma,
    const float* __restrict__ beta, float* __restrict__ out)
{
    __shared__ float red[16];
    __shared__ float s_mu, s_rs;
    const int r = blockIdx.x;
    const int tid = threadIdx.x;

    float4 v;
    if (tid < 128) v = *(const float4*)&g_hf[(size_t)r * ND + (tid << 2)];
    else           v = *(const float4*)&g_hb[(size_t)r * ND + ((tid - 128) << 2)];

    float s = v.x + v.y + v.z + v.w;
    float q = v.x * v.x + v.y * v.y + v.z * v.z + v.w * v.w;
#pragma unroll
    for (int o = 16; o; o >>= 1) {
        s += __shfl_down_sync(0xffffffffu, s, o);
        q += __shfl_down_sync(0xffffffffu, q, o);
    }
    if ((tid & 31) == 0) { red[tid >> 5] = s; red[8 + (tid >> 5)] = q; }
    __syncthreads();
    if (tid == 0) {
        float S = 0.f, Q = 0.f;
#pragma unroll
        for (int i = 0; i < 8; ++i) { S += red[i]; Q += red[8 + i]; }
        float mu = S * (1.f / 1024.f);
        float var = Q * (1.f / 1024.f) - mu * mu;
        s_mu = mu;
        s_rs = rsqrtf(var + 1e-6f);
    }
    __syncthreads();
    float mu = s_mu, rs = s_rs;
    int col = tid << 2;
    float4 g4 = *(const float4*)&gamma[col];
    float4 b4 = *(const float4*)&beta[col];
    float4 xv = *(const float4*)&x[(size_t)r * NI + col];
    float4 o;
    o.x = xv.x + (v.x - mu) * rs * g4.x + b4.x;
    o.y = xv.y + (v.y - mu) * rs * g4.y + b4.y;
    o.z = xv.z + (v.z - mu) * rs * g4.z + b4.z;
    o.w = xv.w + (v.w - mu) * rs * g4.w + b4.w;
    *(float4*)&out[(size_t)r * NI + col] = o;
}

// ---------------- host launch ----------------
extern "C" void kernel_launch(void* const* d_in, const int* in_sizes, int n_in,
                              void* d_out, int out_size)
{
    const float* x     = (const float*)d_in[0];
    const float* W1    = (const float*)d_in[1];
    const float* U1    = (const float*)d_in[2];
    const float* b1    = (const float*)d_in[3];
    const float* Wf    = (const float*)d_in[4];
    const float* Uf    = (const float*)d_in[5];
    const float* bf    = (const float*)d_in[6];
    const float* Wb    = (const float*)d_in[7];
    const float* Ub    = (const float*)d_in[8];
    const float* bb    = (const float*)d_in[9];
    const float* gamma = (const float*)d_in[10];
    const float* beta  = (const float*)d_in[11];
    float* out = (float*)d_out;

    void *p_xw1, *p_xwf, *p_xwb, *p_h1, *p_Wt1, *p_Wtf, *p_Wtb;
    void *p_Ah, *p_Al, *p_Bh1, *p_Bl1, *p_Bhf, *p_Blf, *p_Bhb, *p_Blb;
    cudaGetSymbolAddress(&p_xw1, g_xw1);
    cudaGetSymbolAddress(&p_xwf, g_xwf);
    cudaGetSymbolAddress(&p_xwb, g_xwb);
    cudaGetSymbolAddress(&p_h1,  g_h1);
    cudaGetSymbolAddress(&p_Wt1, g_Wt1);
    cudaGetSymbolAddress(&p_Wtf, g_Wtf);
    cudaGetSymbolAddress(&p_Wtb, g_Wtb);
    cudaGetSymbolAddress(&p_Ah,  g_Ah);
    cudaGetSymbolAddress(&p_Al,  g_Al);
    cudaGetSymbolAddress(&p_Bh1, g_Bh1);
    cudaGetSymbolAddress(&p_Bl1, g_Bl1);
    cudaGetSymbolAddress(&p_Bhf, g_Bhf);
    cudaGetSymbolAddress(&p_Blf, g_Blf);
    cudaGetSymbolAddress(&p_Bhb, g_Bhb);
    cudaGetSymbolAddress(&p_Blb, g_Blb);

    cudaFuncSetAttribute(lstm1_kernel,  cudaFuncAttributeMaxDynamicSharedMemorySize, SMEM_R);
    cudaFuncSetAttribute(lstmfb_kernel, cudaFuncAttributeMaxDynamicSharedMemorySize, SMEM_R);
    cudaFuncSetAttribute(gemm_fp16_kernel, cudaFuncAttributeMaxDynamicSharedMemorySize, SMEM_GEMM);

    const int M = NB * NT;
    dim3 gg(NG / 128, M / 128);

    reset_bars_kernel<<<1, 1>>>();
    transpose_kernel<<<dim3(NG / 32, NI / 32), 256>>>(W1, (float*)p_Wt1, NI, NG);
    transpose_kernel<<<dim3(NG / 32, ND / 32), 256>>>(Wf, (float*)p_Wtf, ND, NG);
    transpose_kernel<<<dim3(NG / 32, ND / 32), 256>>>(Wb, (float*)p_Wtb, ND, NG);

    {
        int n4 = NG * NI / 4;
        split_fp16_kernel<<<(n4 + 255) / 256, 256>>>((const float*)p_Wt1, (uint*)p_Bh1, (uint*)p_Bl1, n4);
        n4 = NG * ND / 4;
        split_fp16_kernel<<<(n4 + 255) / 256, 256>>>((const float*)p_Wtf, (uint*)p_Bhf, (uint*)p_Blf, n4);
        split_fp16_kernel<<<(n4 + 255) / 256, 256>>>((const float*)p_Wtb, (uint*)p_Bhb, (uint*)p_Blb, n4);
        n4 = M * NI / 4;
        split_fp16_kernel<<<(n4 + 255) / 256, 256>>>(x, (uint*)p_Ah, (uint*)p_Al, n4);
    }

    gemm_fp16_kernel<<<gg, 256, SMEM_GEMM>>>((const uint*)p_Ah, (const uint*)p_Al,
                                             (const uint*)p_Bh1, (const uint*)p_Bl1,
                                             b1, (float*)p_xw1, NI / 2);
    lstm1_kernel<<<RCTA, 256, SMEM_R>>>(U1);

    {
        int n4 = M * ND / 4;
        split_fp16_kernel<<<(n4 + 255) / 256, 256>>>((const float*)p_h1, (uint*)p_Ah, (uint*)p_Al, n4);
    }
    gemm_fp16_kernel<<<gg, 256, SMEM_GEMM>>>((const uint*)p_Ah, (const uint*)p_Al,
                                             (const uint*)p_Bhf, (const uint*)p_Blf,
                                             bf, (float*)p_xwf, ND / 2);
    gemm_fp16_kernel<<<gg, 256, SMEM_GEMM>>>((const uint*)p_Ah, (const uint*)p_Al,
                                             (const uint*)p_Bhb, (const uint*)p_Blb,
                                             bb, (float*)p_xwb, ND / 2);
    lstmfb_kernel<<<2 * RCTA, 256, SMEM_R>>>(Uf, Ub);
    ln_kernel<<<M, 256>>>(x, gamma, beta, out);
}

// round 10
// speedup vs baseline: 1.0994x; 1.0994x over previous
#include <cuda_runtime.h>
#include <cuda_fp16.h>
#include <cstdint>

#define NB 64
#define NT 512
#define ND 512
#define NI 1024
#define NG 2048
#define NCTA 128

typedef unsigned long long ull;
typedef unsigned uint;

// ---------------- static device scratch ----------------
__device__ __align__(16) float g_xw1[(size_t)NB * NT * NG];
__device__ __align__(16) float g_xwf[(size_t)NB * NT * NG];
__device__ __align__(16) float g_xwb[(size_t)NB * NT * NG];
__device__ __align__(16) float g_h1 [(size_t)NB * NT * ND];   // [b][t][u]
__device__ __align__(16) float g_hf [(size_t)NB * NT * ND];
__device__ __align__(16) float g_hb [(size_t)NB * NT * ND];
__device__ __align__(16) float g_h1t[(size_t)NT * ND * NB];   // [t][u][b]
__device__ __align__(16) float g_hft[(size_t)NT * ND * NB];
__device__ __align__(16) float g_hbt[(size_t)NT * ND * NB];
__device__ __align__(16) float g_Wt1[(size_t)NG * NI];
__device__ __align__(16) float g_Wtf[(size_t)NG * ND];
__device__ __align__(16) float g_Wtb[(size_t)NG * ND];
// fp16 split GEMM operands
__device__ __align__(16) uint g_Ah [(size_t)NB * NT * NI / 2];
__device__ __align__(16) uint g_Al [(size_t)NB * NT * NI / 2];
__device__ __align__(16) uint g_Bh1[(size_t)NG * NI / 2];
__device__ __align__(16) uint g_Bl1[(size_t)NG * NI / 2];
__device__ __align__(16) uint g_Bhf[(size_t)NG * ND / 2];
__device__ __align__(16) uint g_Blf[(size_t)NG * ND / 2];
__device__ __align__(16) uint g_Bhb[(size_t)NG * ND / 2];
__device__ __align__(16) uint g_Blb[(size_t)NG * ND / 2];
// per-CTA barrier flags, one 128B line per CTA
__device__ __align__(128) unsigned g_flagA[NCTA * 32];
__device__ __align__(128) unsigned g_flagB[NCTA * 32];

// ---------------- packed f32x2 helpers ----------------
__device__ __forceinline__ ull pack2(float lo, float hi) {
    ull v; asm("mov.b64 %0, {%1, %2};" : "=l"(v) : "f"(lo), "f"(hi)); return v;
}
__device__ __forceinline__ float2 unpack2(ull v) {
    float lo, hi; asm("mov.b64 {%0, %1}, %2;" : "=f"(lo), "=f"(hi) : "l"(v));
    return make_float2(lo, hi);
}
__device__ __forceinline__ void ffma2(ull& c, ull a, ull b) {
    asm("fma.rn.f32x2 %0, %1, %2, %0;" : "+l"(c) : "l"(a), "l"(b));
}
__device__ __forceinline__ float sigm(float z) { return 1.f / (1.f + __expf(-z)); }
__device__ __forceinline__ uint pack16(float a, float b) {
    __half2 h = __floats2half2_rn(a, b); return *(uint*)&h;
}
__device__ __forceinline__ float res16(float a) {
    return a - __half2float(__float2half_rn(a));
}

// ---------------- flag-array grid barrier (no same-address atomics) ----------------
__device__ __forceinline__ void flag_barrier(unsigned* flags, int cta, unsigned t, int tid) {
    __syncthreads();
    if (tid == 0) {
        __threadfence();
        ((volatile unsigned*)flags)[cta * 32] = t;
    }
    if (tid < NCTA) {
        while (((volatile unsigned*)flags)[tid * 32] < t) { }
    }
    __syncthreads();
    __threadfence();
}

__global__ void reset_bars_kernel() {
    int i = threadIdx.x;
    if (i < NCTA) { g_flagA[i * 32] = 0u; g_flagB[i * 32] = 0u; }
}

// ---------------- fp16 split: v -> hi + lo (packed pairs) ----------------
__global__ __launch_bounds__(256) void split_fp16_kernel(
    const float* __restrict__ src, uint* __restrict__ hi, uint* __restrict__ lo, int n4)
{
    int i = blockIdx.x * 256 + threadIdx.x;
    if (i >= n4) return;
    float4 v = ((const float4*)src)[i];
    uint2 ho, lo2;
    ho.x = pack16(v.x, v.y); ho.y = pack16(v.z, v.w);
    lo2.x = pack16(res16(v.x), res16(v.y));
    lo2.y = pack16(res16(v.z), res16(v.w));
    ((uint2*)hi)[i] = ho;
    ((uint2*)lo)[i] = lo2;
}

// ================= fp16 mma GEMM (R7 passing version, unchanged) =================
#define KST 12
#define GARRU (128 * KST)
#define GBUFU (4 * GARRU)
#define SMEM_GEMM (2 * GBUFU * 4)

__device__ __forceinline__ void mma_f16(float* d, const uint* a, const uint* b) {
    asm volatile(
        "mma.sync.aligned.m16n8k16.row.col.f32.f16.f16.f32 "
        "{%0,%1,%2,%3}, {%4,%5,%6,%7}, {%8,%9}, {%0,%1,%2,%3};"
        : "+f"(d[0]), "+f"(d[1]), "+f"(d[2]), "+f"(d[3])
        : "r"(a[0]), "r"(a[1]), "r"(a[2]), "r"(a[3]), "r"(b[0]), "r"(b[1]));
}

__global__ __launch_bounds__(256, 1) void gemm_fp16_kernel(
    const uint* __restrict__ Ah, const uint* __restrict__ Al,
    const uint* __restrict__ Bh, const uint* __restrict__ Bl,
    const float* __restrict__ bias, float* __restrict__ C, int K2)
{
    extern __shared__ uint sgu[];
    const int tid = threadIdx.x;
    const int wid = tid >> 5, lane = tid & 31;
    const int lr = lane >> 2, lc = lane & 3;
    const int warp_m = wid & 3, warp_n = wid >> 2;
    const int n0 = blockIdx.x * 128, m0 = blockIdx.y * 128;

    const int row_s = tid >> 1, half = tid & 1;
    const size_t aoff = (size_t)(m0 + row_s) * K2 + half * 4;
    const size_t boff = (size_t)(n0 + row_s) * K2 + half * 4;
    const uint sidx = row_s * KST + half * 4;

    float acc[2][8][4];
#pragma unroll
    for (int mt = 0; mt < 2; ++mt)
#pragma unroll
        for (int nt = 0; nt < 8; ++nt)
#pragma unroll
            for (int q = 0; q < 4; ++q) acc[mt][nt][q] = 0.f;

    const int nc = K2 >> 3;
    uint4 rAh, rAl, rBh, rBl;
    rAh = *(const uint4*)&Ah[aoff];
    rAl = *(const uint4*)&Al[aoff];
    rBh = *(const uint4*)&Bh[boff];
    rBl = *(const uint4*)&Bl[boff];
    *(uint4*)&sgu[0 * GARRU + sidx] = rAh;
    *(uint4*)&sgu[1 * GARRU + sidx] = rAl;
    *(uint4*)&sgu[2 * GARRU + sidx] = rBh;
    *(uint4*)&sgu[3 * GARRU + sidx] = rBl;
    __syncthreads();

#pragma unroll 1
    for (int c = 0; c < nc; ++c) {
        const int buf = c & 1;
        if (c + 1 < nc) {
            rAh = *(const uint4*)&Ah[aoff + (c + 1) * 8];
            rAl = *(const uint4*)&Al[aoff + (c + 1) * 8];
            rBh = *(const uint4*)&Bh[boff + (c + 1) * 8];
            rBl = *(const uint4*)&Bl[boff + (c + 1) * 8];
        }
        const uint* sAh = sgu + buf * GBUFU + 0 * GARRU;
        const uint* sAl = sgu + buf * GBUFU + 1 * GARRU;
        const uint* sBh = sgu + buf * GBUFU + 2 * GARRU;
        const uint* sBl = sgu + buf * GBUFU + 3 * GARRU;

        uint ah[2][4], al[2][4];
#pragma unroll
        for (int mt = 0; mt < 2; ++mt) {
            int row = warp_m * 32 + mt * 16 + lr;
            ah[mt][0] = sAh[row * KST + lc];
            ah[mt][1] = sAh[(row + 8) * KST + lc];
            ah[mt][2] = sAh[row * KST + lc + 4];
            ah[mt][3] = sAh[(row + 8) * KST + lc + 4];
            al[mt][0] = sAl[row * KST + lc];
            al[mt][1] = sAl[(row + 8) * KST + lc];
            al[mt][2] = sAl[row * KST + lc + 4];
            al[mt][3] = sAl[(row + 8) * KST + lc + 4];
        }
        uint bh[8][2], bl[8][2];
#pragma unroll
        for (int nt = 0; nt < 8; ++nt) {
            int n = warp_n * 64 + nt * 8 + lr;
            bh[nt][0] = sBh[n * KST + lc];
            bh[nt][1] = sBh[n * KST + lc + 4];
            bl[nt][0] = sBl[n * KST + lc];
            bl[nt][1] = sBl[n * KST + lc + 4];
        }
#pragma unroll
        for (int mt = 0; mt < 2; ++mt)
#pragma unroll
            for (int nt = 0; nt < 8; ++nt) {
                mma_f16(acc[mt][nt], ah[mt], bh[nt]);
                mma_f16(acc[mt][nt], al[mt], bh[nt]);
                mma_f16(acc[mt][nt], ah[mt], bl[nt]);
            }

        if (c + 1 < nc) {
            const int nb = (c + 1) & 1;
            *(uint4*)&sgu[nb * GBUFU + 0 * GARRU + sidx] = rAh;
            *(uint4*)&sgu[nb * GBUFU + 1 * GARRU + sidx] = rAl;
            *(uint4*)&sgu[nb * GBUFU + 2 * GARRU + sidx] = rBh;
            *(uint4*)&sgu[nb * GBUFU + 3 * GARRU + sidx] = rBl;
        }
        __syncthreads();
    }

#pragma unroll
    for (int mt = 0; mt < 2; ++mt) {
        int row = m0 + warp_m * 32 + mt * 16 + lr;
#pragma unroll
        for (int nt = 0; nt < 8; ++nt) {
            int col = n0 + warp_n * 64 + nt * 8 + 2 * lc;
            float2 bv = *(const float2*)&bias[col];
            float2 o0 = make_float2(acc[mt][nt][0] + bv.x, acc[mt][nt][1] + bv.y);
            float2 o1 = make_float2(acc[mt][nt][2] + bv.x, acc[mt][nt][3] + bv.y);
            *(float2*)&C[(size_t)row * NG + col] = o0;
            *(float2*)&C[(size_t)(row + 8) * NG + col] = o1;
        }
    }
}

// ---------------- weight transpose ----------------
__global__ __launch_bounds__(256) void transpose_kernel(
    const float* __restrict__ W, float* __restrict__ Wt, int K, int N)
{
    __shared__ float t[32][33];
    const int tx = threadIdx.x & 31, ty = threadIdx.x >> 5;
    const int n0 = blockIdx.x << 5, k0 = blockIdx.y << 5;
#pragma unroll
    for (int i = 0; i < 32; i += 8)
        t[ty + i][tx] = W[(size_t)(k0 + ty + i) * N + n0 + tx];
    __syncthreads();
#pragma unroll
    for (int i = 0; i < 32; i += 8)
        Wt[(size_t)(n0 + ty + i) * K + k0 + tx] = t[tx][ty + i];
}

// ================= LSTM recurrence (R4 compute; new barrier; paired fb accums) =================
__device__ __forceinline__ void load_U_shared(float* Us, const float* __restrict__ U,
                                              int u0, int tid) {
    for (int idx = tid; idx < 8192; idx += 256) {
        int k = idx >> 4, r = idx & 15;
        int u = r >> 2, g = r & 3;
        Us[idx] = U[(size_t)k * NG + (size_t)g * ND + u0 + u];
    }
}

__device__ __forceinline__ void stage_ld(float4* r, const float* __restrict__ ht,
                                         int t, int c, int tid) {
    const float4* src = (const float4*)(ht + ((size_t)t * ND + c * 64) * NB);
#pragma unroll
    for (int j = 0; j < 4; ++j) r[j] = src[j * 256 + tid];
}

__device__ __forceinline__ void stage_st(float* dst, const float4* r, int tid) {
#pragma unroll
    for (int j = 0; j < 4; ++j) {
        int flat = j * 256 + tid;
        int kl = flat >> 4, b4 = (flat & 15) << 2;
        *(float4*)&dst[kl * 64 + b4] = r[j];
    }
}

__device__ __forceinline__ void compute_chunk(const float* hs, const float* Us,
                                              int c, int ke, int b2, ull* acc) {
#pragma unroll
    for (int ii = 0; ii < 8; ++ii) {
        int kl = ii * 8 + ke;
        float2 hv = *(const float2*)&hs[kl * 64 + (b2 << 1)];
        ull a0 = pack2(hv.x, hv.x);
        ull a1 = pack2(hv.y, hv.y);
        const ulonglong2* uvp = (const ulonglong2*)&Us[(((c << 6) + kl) << 4)];
#pragma unroll
        for (int u = 0; u < 4; ++u) {
            ulonglong2 uv = uvp[u];
            ffma2(acc[(0 * 4 + u) * 2 + 0], a0, uv.x);
            ffma2(acc[(0 * 4 + u) * 2 + 1], a0, uv.y);
            ffma2(acc[(1 * 4 + u) * 2 + 0], a1, uv.x);
            ffma2(acc[(1 * 4 + u) * 2 + 1], a1, uv.y);
        }
    }
}

__device__ __forceinline__ void accum(const float* __restrict__ ht, int t,
                                      const float* Us, float* h0, float* h1b,
                                      int tid, int ke, int b2, ull* acc) {
    float4 r[4];
    stage_ld(r, ht, t, 0, tid);
    stage_st(h0, r, tid);
    __syncthreads();
#pragma unroll 1
    for (int c = 0; c < 8; ++c) {
        const float* cur = (c & 1) ? h1b : h0;
        float* nxt = (c & 1) ? h0 : h1b;
        if (c < 7) stage_ld(r, ht, t, c + 1, tid);
        compute_chunk(cur, Us, c, ke, b2, acc);
        if (c < 7) stage_st(nxt, r, tid);
        __syncthreads();
    }
}

// paired fwd+bwd accumulation: shared syncs, overlapped loads
__device__ __forceinline__ void accum_pair(
    const float* __restrict__ htf, int tf, const float* Usf,
    const float* __restrict__ htb, int tb, const float* Usb,
    float* hA, float* hB, float* hC, float* hD,
    int tid, int ke, int b2, ull* accf, ull* accb)
{
    float4 rf[4], rb[4];
    stage_ld(rf, htf, tf, 0, tid);
    stage_ld(rb, htb, tb, 0, tid);
    stage_st(hA, rf, tid);
    stage_st(hC, rb, tid);
    __syncthreads();
#pragma unroll 1
    for (int c = 0; c < 8; ++c) {
        const float* curf = (c & 1) ? hB : hA;
        float* nxtf = (c & 1) ? hA : hB;
        const float* curb = (c & 1) ? hD : hC;
        float* nxtb = (c & 1) ? hC : hD;
        if (c < 7) { stage_ld(rf, htf, tf, c + 1, tid); stage_ld(rb, htb, tb, c + 1, tid); }
        compute_chunk(curf, Usf, c, ke, b2, accf);
        compute_chunk(curb, Usb, c, ke, b2, accb);
        if (c < 7) { stage_st(nxtf, rf, tid); stage_st(nxtb, rb, tid); }
        __syncthreads();
    }
}

__device__ __forceinline__ void stage_zs(float* zs, const float* __restrict__ xw,
                                         int t, int u0, int tid) {
    int bb = tid >> 2, g = tid & 3;
    float4 xv = *(const float4*)&xw[((size_t)bb * NT + t) * NG + (size_t)g * ND + u0];
    *(float4*)&zs[bb * 20 + (g << 2)] = xv;
}

__device__ __forceinline__ void gate(float* __restrict__ h_btu, float* __restrict__ h_tub,
                                     int t, int u0, const ull* acc, float& cst,
                                     const float* zs, float* scr, float* shs,
                                     int tid, int ke, int b2, int gb, int gu) {
    ull* scr_u = (ull*)scr;
#pragma unroll
    for (int bb = 0; bb < 2; ++bb)
#pragma unroll
        for (int u = 0; u < 4; ++u)
#pragma unroll
            for (int p = 0; p < 2; ++p)
                scr_u[(size_t)(((b2 << 1) | bb) * 66 + (ke << 3) + (u << 1) + p)] =
                    acc[(bb * 4 + u) * 2 + p];
    __syncthreads();

    float4 z = make_float4(0.f, 0.f, 0.f, 0.f);
#pragma unroll
    for (int k = 0; k < 8; ++k) {
        float4 part = *(const float4*)&scr[gb * 132 + (k << 4) + (gu << 2)];
        z.x += part.x; z.y += part.y; z.z += part.z; z.w += part.w;
    }
    float zi = z.x + zs[gb * 20 + gu];
    float zf = z.y + zs[gb * 20 + 4 + gu];
    float zg = z.z + zs[gb * 20 + 8 + gu];
    float zo = z.w + zs[gb * 20 + 12 + gu];
    float ig = sigm(zi), fg = sigm(zf);
    float gv = fmaxf(zg, 0.f), og = sigm(zo);
    cst = fmaf(fg, cst, ig * gv);
    float h = og * fmaxf(cst, 0.f);

    h_tub[((size_t)t * ND + u0 + gu) * NB + gb] = h;
    shs[(gb << 2) + gu] = h;
    __syncthreads();
    if (tid < 64) {
        float4 h4 = *(const float4*)&shs[tid << 2];
        *(float4*)&h_btu[((size_t)tid * NT + t) * ND + u0] = h4;
    }
}

#define SMEM_L1 (26368 * 4)

__global__ __launch_bounds__(256) void lstm1_kernel(const float* __restrict__ U)
{
    extern __shared__ float sm[];
    float* Us  = sm;
    float* hA  = sm + 8192;
    float* hB  = sm + 12288;
    float* zs  = sm + 16384;
    float* scr = sm + 17664;
    float* shs = sm + 26112;

    const int tid = threadIdx.x;
    const int ke = tid >> 5, b2 = tid & 31;
    const int gb = tid & 63, gu = tid >> 6;
    const int u0 = blockIdx.x << 2;

    load_U_shared(Us, U, u0, tid);
    __syncthreads();

    float cst = 0.f;
    for (int t = 0; t < NT; ++t) {
        stage_zs(zs, g_xw1, t, u0, tid);
        ull acc16[16];
#pragma unroll
        for (int i = 0; i < 16; ++i) acc16[i] = 0ull;
        if (t > 0) {
            flag_barrier(g_flagA, blockIdx.x, (unsigned)t, tid);
            accum(g_h1t, t - 1, Us, hA, hB, tid, ke, b2, acc16);
        } else {
            __syncthreads();
        }
        gate(g_h1, g_h1t, t, u0, acc16, cst, zs, scr, shs, tid, ke, b2, gb, gu);
    }
}

// smem floats: Ufs 8192 | Ubs 8192 | hA..hD 4x4096 | zsf 1280 | zsb 1280 | scr 8448 | shs 256
#define SMEM_FB (44032 * 4)

__global__ __launch_bounds__(256) void lstmfb_kernel(
    const float* __restrict__ Uf, const float* __restrict__ Ub)
{
    extern __shared__ float sm[];
    float* Ufs = sm;
    float* Ubs = sm + 8192;
    float* hA  = sm + 16384;
    float* hB  = sm + 20480;
    float* hC  = sm + 24576;
    float* hD  = sm + 28672;
    float* zsf = sm + 32768;
    float* zsb = sm + 34048;
    float* scr = sm + 35328;
    float* shs = sm + 43776;

    const int tid = threadIdx.x;
    const int ke = tid >> 5, b2 = tid & 31;
    const int gb = tid & 63, gu = tid >> 6;
    const int u0 = blockIdx.x << 2;

    load_U_shared(Ufs, Uf, u0, tid);
    load_U_shared(Ubs, Ub, u0, tid);
    __syncthreads();

    float cf = 0.f, cb = 0.f;
    for (int s = 0; s < NT; ++s) {
        int tf = s, tb = NT - 1 - s;
        stage_zs(zsf, g_xwf, tf, u0, tid);
        stage_zs(zsb, g_xwb, tb, u0, tid);
        ull af[16], ab[16];
#pragma unroll
        for (int i = 0; i < 16; ++i) { af[i] = 0ull; ab[i] = 0ull; }
        if (s > 0) {
            flag_barrier(g_flagB, blockIdx.x, (unsigned)s, tid);
            accum_pair(g_hft, tf - 1, Ufs, g_hbt, tb + 1, Ubs,
                       hA, hB, hC, hD, tid, ke, b2, af, ab);
        } else {
            __syncthreads();
        }
        gate(g_hf, g_hft, tf, u0, af, cf, zsf, scr, shs, tid, ke, b2, gb, gu);
        gate(g_hb, g_hbt, tb, u0, ab, cb, zsb, scr, shs, tid, ke, b2, gb, gu);
    }
}

// ---------------- LayerNorm + residual ----------------
__global__ __launch_bounds__(256) void ln_kernel(
    const float* __restrict__ x, const float* __restrict__ gamma,
    const float* __restrict__ beta, float* __restrict__ out)
{
    __shared__ float red[16];
    __shared__ float s_mu, s_rs;
    const int r = blockIdx.x;
    const int tid = threadIdx.x;

    float4 v;
    if (tid < 128) v = *(const float4*)&g_hf[(size_t)r * ND + (tid << 2)];
    else           v = *(const float4*)&g_hb[(size_t)r * ND + ((tid - 128) << 2)];

    float s = v.x + v.y + v.z + v.w;
    float q = v.x * v.x + v.y * v.y + v.z * v.z + v.w * v.w;
#pragma unroll
    for (int o = 16; o; o >>= 1) {
        s += __shfl_down_sync(0xffffffffu, s, o);
        q += __shfl_down_sync(0xffffffffu, q, o);
    }
    if ((tid & 31) == 0) { red[tid >> 5] = s; red[8 + (tid >> 5)] = q; }
    __syncthreads();
    if (tid == 0) {
        float S = 0.f, Q = 0.f;
#pragma unroll
        for (int i = 0; i < 8; ++i) { S += red[i]; Q += red[8 + i]; }
        float mu = S * (1.f / 1024.f);
        float var = Q * (1.f / 1024.f) - mu * mu;
        s_mu = mu;
        s_rs = rsqrtf(var + 1e-6f);
    }
    __syncthreads();
    float mu = s_mu, rs = s_rs;
    int col = tid << 2;
    float4 g4 = *(const float4*)&gamma[col];
    float4 b4 = *(const float4*)&beta[col];
    float4 xv = *(const float4*)&x[(size_t)r * NI + col];
    float4 o;
    o.x = xv.x + (v.x - mu) * rs * g4.x + b4.x;
    o.y = xv.y + (v.y - mu) * rs * g4.y + b4.y;
    o.z = xv.z + (v.z - mu) * rs * g4.z + b4.z;
    o.w = xv.w + (v.w - mu) * rs * g4.w + b4.w;
    *(float4*)&out[(size_t)r * NI + col] = o;
}

// ---------------- host launch ----------------
extern "C" void kernel_launch(void* const* d_in, const int* in_sizes, int n_in,
                              void* d_out, int out_size)
{
    const float* x     = (const float*)d_in[0];
    const float* W1    = (const float*)d_in[1];
    const float* U1    = (const float*)d_in[2];
    const float* b1    = (const float*)d_in[3];
    const float* Wf    = (const float*)d_in[4];
    const float* Uf    = (const float*)d_in[5];
    const float* bf    = (const float*)d_in[6];
    const float* Wb    = (const float*)d_in[7];
    const float* Ub    = (const float*)d_in[8];
    const float* bb    = (const float*)d_in[9];
    const float* gamma = (const float*)d_in[10];
    const float* beta  = (const float*)d_in[11];
    float* out = (float*)d_out;

    void *p_xw1, *p_xwf, *p_xwb, *p_h1, *p_Wt1, *p_Wtf, *p_Wtb;
    void *p_Ah, *p_Al, *p_Bh1, *p_Bl1, *p_Bhf, *p_Blf, *p_Bhb, *p_Blb;
    cudaGetSymbolAddress(&p_xw1, g_xw1);
    cudaGetSymbolAddress(&p_xwf, g_xwf);
    cudaGetSymbolAddress(&p_xwb, g_xwb);
    cudaGetSymbolAddress(&p_h1,  g_h1);
    cudaGetSymbolAddress(&p_Wt1, g_Wt1);
    cudaGetSymbolAddress(&p_Wtf, g_Wtf);
    cudaGetSymbolAddress(&p_Wtb, g_Wtb);
    cudaGetSymbolAddress(&p_Ah,  g_Ah);
    cudaGetSymbolAddress(&p_Al,  g_Al);
    cudaGetSymbolAddress(&p_Bh1, g_Bh1);
    cudaGetSymbolAddress(&p_Bl1, g_Bl1);
    cudaGetSymbolAddress(&p_Bhf, g_Bhf);
    cudaGetSymbolAddress(&p_Blf, g_Blf);
    cudaGetSymbolAddress(&p_Bhb, g_Bhb);
    cudaGetSymbolAddress(&p_Blb, g_Blb);

    cudaFuncSetAttribute(lstm1_kernel,  cudaFuncAttributeMaxDynamicSharedMemorySize, SMEM_L1);
    cudaFuncSetAttribute(lstmfb_kernel, cudaFuncAttributeMaxDynamicSharedMemorySize, SMEM_FB);
    cudaFuncSetAttribute(gemm_fp16_kernel, cudaFuncAttributeMaxDynamicSharedMemorySize, SMEM_GEMM);

    const int M = NB * NT;
    dim3 gg(NG / 128, M / 128);

    reset_bars_kernel<<<1, 256>>>();
    transpose_kernel<<<dim3(NG / 32, NI / 32), 256>>>(W1, (float*)p_Wt1, NI, NG);
    transpose_kernel<<<dim3(NG / 32, ND / 32), 256>>>(Wf, (float*)p_Wtf, ND, NG);
    transpose_kernel<<<dim3(NG / 32, ND / 32), 256>>>(Wb, (float*)p_Wtb, ND, NG);

    {
        int n4 = NG * NI / 4;
        split_fp16_kernel<<<(n4 + 255) / 256, 256>>>((const float*)p_Wt1, (uint*)p_Bh1, (uint*)p_Bl1, n4);
        n4 = NG * ND / 4;
        split_fp16_kernel<<<(n4 + 255) / 256, 256>>>((const float*)p_Wtf, (uint*)p_Bhf, (uint*)p_Blf, n4);
        split_fp16_kernel<<<(n4 + 255) / 256, 256>>>((const float*)p_Wtb, (uint*)p_Bhb, (uint*)p_Blb, n4);
        n4 = M * NI / 4;
        split_fp16_kernel<<<(n4 + 255) / 256, 256>>>(x, (uint*)p_Ah, (uint*)p_Al, n4);
    }

    gemm_fp16_kernel<<<gg, 256, SMEM_GEMM>>>((const uint*)p_Ah, (const uint*)p_Al,
                                             (const uint*)p_Bh1, (const uint*)p_Bl1,
                                             b1, (float*)p_xw1, NI / 2);
    lstm1_kernel<<<NCTA, 256, SMEM_L1>>>(U1);

    {
        int n4 = M * ND / 4;
        split_fp16_kernel<<<(n4 + 255) / 256, 256>>>((const float*)p_h1, (uint*)p_Ah, (uint*)p_Al, n4);
    }
    gemm_fp16_kernel<<<gg, 256, SMEM_GEMM>>>((const uint*)p_Ah, (const uint*)p_Al,
                                             (const uint*)p_Bhf, (const uint*)p_Blf,
                                             bf, (float*)p_xwf, ND / 2);
    gemm_fp16_kernel<<<gg, 256, SMEM_GEMM>>>((const uint*)p_Ah, (const uint*)p_Al,
                                             (const uint*)p_Bhb, (const uint*)p_Blb,
                                             bb, (float*)p_xwb, ND / 2);
    lstmfb_kernel<<<NCTA, 256, SMEM_FB>>>(Uf, Ub);
    ln_kernel<<<M, 256>>>(x, gamma, beta, out);
}

// round 12
// speedup vs baseline: 1.1145x; 1.0137x over previous
#include <cuda_runtime.h>
#include <cuda_fp16.h>
#include <cstdint>

#define NB 64
#define NT 512
#define ND 512
#define NI 1024
#define NG 2048
#define NCTA 128

typedef unsigned long long ull;
typedef unsigned uint;

// ---------------- static device scratch ----------------
__device__ __align__(16) float g_xw1[(size_t)NB * NT * NG];
__device__ __align__(16) float g_xwf[(size_t)NB * NT * NG];
__device__ __align__(16) float g_xwb[(size_t)NB * NT * NG];
__device__ __align__(16) float g_h1 [(size_t)NB * NT * ND];   // [b][t][u]
__device__ __align__(16) float g_hf [(size_t)NB * NT * ND];
__device__ __align__(16) float g_hb [(size_t)NB * NT * ND];
__device__ __align__(16) float g_h1t[(size_t)NT * ND * NB];   // [t][u][b]
__device__ __align__(16) float g_hft[(size_t)NT * ND * NB];
__device__ __align__(16) float g_hbt[(size_t)NT * ND * NB];
__device__ __align__(16) float g_Wt1[(size_t)NG * NI];
__device__ __align__(16) float g_Wtf[(size_t)NG * ND];
__device__ __align__(16) float g_Wtb[(size_t)NG * ND];
// fp16 split GEMM operands
__device__ __align__(16) uint g_Ah [(size_t)NB * NT * NI / 2];
__device__ __align__(16) uint g_Al [(size_t)NB * NT * NI / 2];
__device__ __align__(16) uint g_Bh1[(size_t)NG * NI / 2];
__device__ __align__(16) uint g_Bl1[(size_t)NG * NI / 2];
__device__ __align__(16) uint g_Bhf[(size_t)NG * ND / 2];
__device__ __align__(16) uint g_Blf[(size_t)NG * ND / 2];
__device__ __align__(16) uint g_Bhb[(size_t)NG * ND / 2];
__device__ __align__(16) uint g_Blb[(size_t)NG * ND / 2];
__device__ unsigned g_bar1;
__device__ unsigned g_barf;
__device__ unsigned g_barb;

// ---------------- packed f32x2 helpers ----------------
__device__ __forceinline__ ull pack2(float lo, float hi) {
    ull v; asm("mov.b64 %0, {%1, %2};" : "=l"(v) : "f"(lo), "f"(hi)); return v;
}
__device__ __forceinline__ float2 unpack2(ull v) {
    float lo, hi; asm("mov.b64 {%0, %1}, %2;" : "=f"(lo), "=f"(hi) : "l"(v));
    return make_float2(lo, hi);
}
__device__ __forceinline__ void ffma2(ull& c, ull a, ull b) {
    asm("fma.rn.f32x2 %0, %1, %2, %0;" : "+l"(c) : "l"(a), "l"(b));
}
__device__ __forceinline__ float sigm(float z) { return 1.f / (1.f + __expf(-z)); }
__device__ __forceinline__ uint pack16(float a, float b) {
    __half2 h = __floats2half2_rn(a, b); return *(uint*)&h;
}
__device__ __forceinline__ float res16(float a) {
    return a - __half2float(__float2half_rn(a));
}

#define BARH(id) asm volatile("bar.sync %0, 128;" :: "r"(id) : "memory")

// ---------------- grid barrier (whole CTA, single-line atomic) ----------------
__device__ __forceinline__ void grid_barrier(unsigned* bar, unsigned target) {
    __threadfence();
    __syncthreads();
    if (threadIdx.x == 0) {
        atomicAdd(bar, 1u);
        while (*((volatile unsigned*)bar) < target) __nanosleep(32);
        __threadfence();
    }
    __syncthreads();
}

// half-CTA grid barrier: 128 threads, named barrier, own counter
__device__ __forceinline__ void half_grid_barrier(unsigned* bar, unsigned target,
                                                  int ltid, int barid) {
    __threadfence();
    BARH(barid);
    if (ltid == 0) {
        atomicAdd(bar, 1u);
        while (*((volatile unsigned*)bar) < target) __nanosleep(32);
        __threadfence();
    }
    BARH(barid);
}

__global__ void reset_bars_kernel() { g_bar1 = 0u; g_barf = 0u; g_barb = 0u; }

// ---------------- fp16 split: v -> hi + lo (packed pairs) ----------------
__global__ __launch_bounds__(256) void split_fp16_kernel(
    const float* __restrict__ src, uint* __restrict__ hi, uint* __restrict__ lo, int n4)
{
    int i = blockIdx.x * 256 + threadIdx.x;
    if (i >= n4) return;
    float4 v = ((const float4*)src)[i];
    uint2 ho, lo2;
    ho.x = pack16(v.x, v.y); ho.y = pack16(v.z, v.w);
    lo2.x = pack16(res16(v.x), res16(v.y));
    lo2.y = pack16(res16(v.z), res16(v.w));
    ((uint2*)hi)[i] = ho;
    ((uint2*)lo)[i] = lo2;
}

// ================= fp16 mma GEMM (R7 passing version, unchanged) =================
#define KST 12
#define GARRU (128 * KST)
#define GBUFU (4 * GARRU)
#define SMEM_GEMM (2 * GBUFU * 4)

__device__ __forceinline__ void mma_f16(float* d, const uint* a, const uint* b) {
    asm volatile(
        "mma.sync.aligned.m16n8k16.row.col.f32.f16.f16.f32 "
        "{%0,%1,%2,%3}, {%4,%5,%6,%7}, {%8,%9}, {%0,%1,%2,%3};"
        : "+f"(d[0]), "+f"(d[1]), "+f"(d[2]), "+f"(d[3])
        : "r"(a[0]), "r"(a[1]), "r"(a[2]), "r"(a[3]), "r"(b[0]), "r"(b[1]));
}

__global__ __launch_bounds__(256, 1) void gemm_fp16_kernel(
    const uint* __restrict__ Ah, const uint* __restrict__ Al,
    const uint* __restrict__ Bh, const uint* __restrict__ Bl,
    const float* __restrict__ bias, float* __restrict__ C, int K2)
{
    extern __shared__ uint sgu[];
    const int tid = threadIdx.x;
    const int wid = tid >> 5, lane = tid & 31;
    const int lr = lane >> 2, lc = lane & 3;
    const int warp_m = wid & 3, warp_n = wid >> 2;
    const int n0 = blockIdx.x * 128, m0 = blockIdx.y * 128;

    const int row_s = tid >> 1, half = tid & 1;
    const size_t aoff = (size_t)(m0 + row_s) * K2 + half * 4;
    const size_t boff = (size_t)(n0 + row_s) * K2 + half * 4;
    const uint sidx = row_s * KST + half * 4;

    float acc[2][8][4];
#pragma unroll
    for (int mt = 0; mt < 2; ++mt)
#pragma unroll
        for (int nt = 0; nt < 8; ++nt)
#pragma unroll
            for (int q = 0; q < 4; ++q) acc[mt][nt][q] = 0.f;

    const int nc = K2 >> 3;
    uint4 rAh, rAl, rBh, rBl;
    rAh = *(const uint4*)&Ah[aoff];
    rAl = *(const uint4*)&Al[aoff];
    rBh = *(const uint4*)&Bh[boff];
    rBl = *(const uint4*)&Bl[boff];
    *(uint4*)&sgu[0 * GARRU + sidx] = rAh;
    *(uint4*)&sgu[1 * GARRU + sidx] = rAl;
    *(uint4*)&sgu[2 * GARRU + sidx] = rBh;
    *(uint4*)&sgu[3 * GARRU + sidx] = rBl;
    __syncthreads();

#pragma unroll 1
    for (int c = 0; c < nc; ++c) {
        const int buf = c & 1;
        if (c + 1 < nc) {
            rAh = *(const uint4*)&Ah[aoff + (c + 1) * 8];
            rAl = *(const uint4*)&Al[aoff + (c + 1) * 8];
            rBh = *(const uint4*)&Bh[boff + (c + 1) * 8];
            rBl = *(const uint4*)&Bl[boff + (c + 1) * 8];
        }
        const uint* sAh = sgu + buf * GBUFU + 0 * GARRU;
        const uint* sAl = sgu + buf * GBUFU + 1 * GARRU;
        const uint* sBh = sgu + buf * GBUFU + 2 * GARRU;
        const uint* sBl = sgu + buf * GBUFU + 3 * GARRU;

        uint ah[2][4], al[2][4];
#pragma unroll
        for (int mt = 0; mt < 2; ++mt) {
            int row = warp_m * 32 + mt * 16 + lr;
            ah[mt][0] = sAh[row * KST + lc];
            ah[mt][1] = sAh[(row + 8) * KST + lc];
            ah[mt][2] = sAh[row * KST + lc + 4];
            ah[mt][3] = sAh[(row + 8) * KST + lc + 4];
            al[mt][0] = sAl[row * KST + lc];
            al[mt][1] = sAl[(row + 8) * KST + lc];
            al[mt][2] = sAl[row * KST + lc + 4];
            al[mt][3] = sAl[(row + 8) * KST + lc + 4];
        }
        uint bh[8][2], bl[8][2];
#pragma unroll
        for (int nt = 0; nt < 8; ++nt) {
            int n = warp_n * 64 + nt * 8 + lr;
            bh[nt][0] = sBh[n * KST + lc];
            bh[nt][1] = sBh[n * KST + lc + 4];
            bl[nt][0] = sBl[n * KST + lc];
            bl[nt][1] = sBl[n * KST + lc + 4];
        }
#pragma unroll
        for (int mt = 0; mt < 2; ++mt)
#pragma unroll
            for (int nt = 0; nt < 8; ++nt) {
                mma_f16(acc[mt][nt], ah[mt], bh[nt]);
                mma_f16(acc[mt][nt], al[mt], bh[nt]);
                mma_f16(acc[mt][nt], ah[mt], bl[nt]);
            }

        if (c + 1 < nc) {
            const int nb = (c + 1) & 1;
            *(uint4*)&sgu[nb * GBUFU + 0 * GARRU + sidx] = rAh;
            *(uint4*)&sgu[nb * GBUFU + 1 * GARRU + sidx] = rAl;
            *(uint4*)&sgu[nb * GBUFU + 2 * GARRU + sidx] = rBh;
            *(uint4*)&sgu[nb * GBUFU + 3 * GARRU + sidx] = rBl;
        }
        __syncthreads();
    }

#pragma unroll
    for (int mt = 0; mt < 2; ++mt) {
        int row = m0 + warp_m * 32 + mt * 16 + lr;
#pragma unroll
        for (int nt = 0; nt < 8; ++nt) {
            int col = n0 + warp_n * 64 + nt * 8 + 2 * lc;
            float2 bv = *(const float2*)&bias[col];
            float2 o0 = make_float2(acc[mt][nt][0] + bv.x, acc[mt][nt][1] + bv.y);
            float2 o1 = make_float2(acc[mt][nt][2] + bv.x, acc[mt][nt][3] + bv.y);
            *(float2*)&C[(size_t)row * NG + col] = o0;
            *(float2*)&C[(size_t)(row + 8) * NG + col] = o1;
        }
    }
}

// ---------------- weight transpose ----------------
__global__ __launch_bounds__(256) void transpose_kernel(
    const float* __restrict__ W, float* __restrict__ Wt, int K, int N)
{
    __shared__ float t[32][33];
    const int tx = threadIdx.x & 31, ty = threadIdx.x >> 5;
    const int n0 = blockIdx.x << 5, k0 = blockIdx.y << 5;
#pragma unroll
    for (int i = 0; i < 32; i += 8)
        t[ty + i][tx] = W[(size_t)(k0 + ty + i) * N + n0 + tx];
    __syncthreads();
#pragma unroll
    for (int i = 0; i < 32; i += 8)
        Wt[(size_t)(n0 + ty + i) * K + k0 + tx] = t[tx][ty + i];
}

// ================= LSTM1 (R7 256-thread design, unchanged) =================
__device__ __forceinline__ void load_U_shared(float* Us, const float* __restrict__ U,
                                              int u0, int tid, int nthr) {
    for (int idx = tid; idx < 8192; idx += nthr) {
        int k = idx >> 4, r = idx & 15;
        int u = r >> 2, g = r & 3;
        Us[idx] = U[(size_t)k * NG + (size_t)g * ND + u0 + u];
    }
}

__device__ __forceinline__ void stage_ld(float4* r, const float* __restrict__ ht,
                                         int t, int c, int tid) {
    const float4* src = (const float4*)(ht + ((size_t)t * ND + c * 64) * NB);
#pragma unroll
    for (int j = 0; j < 4; ++j) r[j] = src[j * 256 + tid];
}

__device__ __forceinline__ void stage_st(float* dst, const float4* r, int tid) {
#pragma unroll
    for (int j = 0; j < 4; ++j) {
        int flat = j * 256 + tid;
        int kl = flat >> 4, b4 = (flat & 15) << 2;
        *(float4*)&dst[kl * 64 + b4] = r[j];
    }
}

__device__ __forceinline__ void compute_chunk(const float* hs, const float* Us,
                                              int c, int ke, int b2, ull* acc) {
#pragma unroll
    for (int ii = 0; ii < 8; ++ii) {
        int kl = ii * 8 + ke;
        float2 hv = *(const float2*)&hs[kl * 64 + (b2 << 1)];
        ull a0 = pack2(hv.x, hv.x);
        ull a1 = pack2(hv.y, hv.y);
        const ulonglong2* uvp = (const ulonglong2*)&Us[(((c << 6) + kl) << 4)];
#pragma unroll
        for (int u = 0; u < 4; ++u) {
            ulonglong2 uv = uvp[u];
            ffma2(acc[(0 * 4 + u) * 2 + 0], a0, uv.x);
            ffma2(acc[(0 * 4 + u) * 2 + 1], a0, uv.y);
            ffma2(acc[(1 * 4 + u) * 2 + 0], a1, uv.x);
            ffma2(acc[(1 * 4 + u) * 2 + 1], a1, uv.y);
        }
    }
}

__device__ __forceinline__ void accum(const float* __restrict__ ht, int t,
                                      const float* Us, float* h0, float* h1b,
                                      int tid, int ke, int b2, ull* acc) {
    float4 r[4];
    stage_ld(r, ht, t, 0, tid);
    stage_st(h0, r, tid);
    __syncthreads();
#pragma unroll 1
    for (int c = 0; c < 8; ++c) {
        const float* cur = (c & 1) ? h1b : h0;
        float* nxt = (c & 1) ? h0 : h1b;
        if (c < 7) stage_ld(r, ht, t, c + 1, tid);
        compute_chunk(cur, Us, c, ke, b2, acc);
        if (c < 7) stage_st(nxt, r, tid);
        __syncthreads();
    }
}

__device__ __forceinline__ void stage_zs(float* zs, const float* __restrict__ xw,
                                         int t, int u0, int tid) {
    int bb = tid >> 2, g = tid & 3;
    float4 xv = *(const float4*)&xw[((size_t)bb * NT + t) * NG + (size_t)g * ND + u0];
    *(float4*)&zs[bb * 20 + (g << 2)] = xv;
}

__device__ __forceinline__ void gate(float* __restrict__ h_btu, float* __restrict__ h_tub,
                                     int t, int u0, const ull* acc, float& cst,
                                     const float* zs, float* scr, float* shs,
                                     int tid, int ke, int b2, int gb, int gu) {
    ull* scr_u = (ull*)scr;
#pragma unroll
    for (int bb = 0; bb < 2; ++bb)
#pragma unroll
        for (int u = 0; u < 4; ++u)
#pragma unroll
            for (int p = 0; p < 2; ++p)
                scr_u[(size_t)(((b2 << 1) | bb) * 66 + (ke << 3) + (u << 1) + p)] =
                    acc[(bb * 4 + u) * 2 + p];
    __syncthreads();

    float4 z = make_float4(0.f, 0.f, 0.f, 0.f);
#pragma unroll
    for (int k = 0; k < 8; ++k) {
        float4 part = *(const float4*)&scr[gb * 132 + (k << 4) + (gu << 2)];
        z.x += part.x; z.y += part.y; z.z += part.z; z.w += part.w;
    }
    float zi = z.x + zs[gb * 20 + gu];
    float zf = z.y + zs[gb * 20 + 4 + gu];
    float zg = z.z + zs[gb * 20 + 8 + gu];
    float zo = z.w + zs[gb * 20 + 12 + gu];
    float ig = sigm(zi), fg = sigm(zf);
    float gv = fmaxf(zg, 0.f), og = sigm(zo);
    cst = fmaf(fg, cst, ig * gv);
    float h = og * fmaxf(cst, 0.f);

    h_tub[((size_t)t * ND + u0 + gu) * NB + gb] = h;
    shs[(gb << 2) + gu] = h;
    __syncthreads();
    if (tid < 64) {
        float4 h4 = *(const float4*)&shs[tid << 2];
        *(float4*)&h_btu[((size_t)tid * NT + t) * ND + u0] = h4;
    }
}

#define SMEM_L1 (26368 * 4)

__global__ __launch_bounds__(256) void lstm1_kernel(const float* __restrict__ U)
{
    extern __shared__ float sm[];
    float* Us  = sm;
    float* hA  = sm + 8192;
    float* hB  = sm + 12288;
    float* zs  = sm + 16384;
    float* scr = sm + 17664;
    float* shs = sm + 26112;

    const int tid = threadIdx.x;
    const int ke = tid >> 5, b2 = tid & 31;
    const int gb = tid & 63, gu = tid >> 6;
    const int u0 = blockIdx.x << 2;

    load_U_shared(Us, U, u0, tid, 256);
    __syncthreads();

    float cst = 0.f;
    for (int t = 0; t < NT; ++t) {
        stage_zs(zs, g_xw1, t, u0, tid);
        ull acc16[16];
#pragma unroll
        for (int i = 0; i < 16; ++i) acc16[i] = 0ull;
        if (t > 0) {
            grid_barrier(&g_bar1, (unsigned)t * NCTA);
            accum(g_h1t, t - 1, Us, hA, hB, tid, ke, b2, acc16);
        } else {
            __syncthreads();
        }
        gate(g_h1, g_h1t, t, u0, acc16, cst, zs, scr, shs, tid, ke, b2, gb, gu);
    }
}

// ================= fused fb LSTM: concurrent half-CTA directions =================
// warps 0-3 = forward, warps 4-7 = backward. Each half: 128 threads, 4 units,
// k split across 4 warps (128 k-iters/thread), own SMEM regions + named barriers.

__device__ __forceinline__ void stage_ld8(float4* r, const float* __restrict__ ht,
                                          int t, int c, int ltid) {
    const float4* src = (const float4*)(ht + ((size_t)t * ND + c * 64) * NB);
#pragma unroll
    for (int j = 0; j < 8; ++j) r[j] = src[j * 128 + ltid];
}

__device__ __forceinline__ void stage_st8(float* dst, const float4* r, int ltid) {
#pragma unroll
    for (int j = 0; j < 8; ++j) {
        int flat = j * 128 + ltid;
        int kl = flat >> 4, b4 = (flat & 15) << 2;
        *(float4*)&dst[kl * 64 + b4] = r[j];
    }
}

__device__ __forceinline__ void compute_chunk128(const float* hs, const float* Us,
                                                 int c, int ke, int b2, ull* acc) {
#pragma unroll
    for (int ii = 0; ii < 16; ++ii) {
        int kl = ii * 4 + ke;
        float2 hv = *(const float2*)&hs[kl * 64 + (b2 << 1)];
        ull a0 = pack2(hv.x, hv.x);
        ull a1 = pack2(hv.y, hv.y);
        const ulonglong2* uvp = (const ulonglong2*)&Us[(((c << 6) + kl) << 4)];
#pragma unroll
        for (int u = 0; u < 4; ++u) {
            ulonglong2 uv = uvp[u];
            ffma2(acc[(0 * 4 + u) * 2 + 0], a0, uv.x);
            ffma2(acc[(0 * 4 + u) * 2 + 1], a0, uv.y);
            ffma2(acc[(1 * 4 + u) * 2 + 0], a1, uv.x);
            ffma2(acc[(1 * 4 + u) * 2 + 1], a1, uv.y);
        }
    }
}

__device__ __forceinline__ void accum128(const float* __restrict__ ht, int t,
                                         const float* Us, float* h0, float* h1b,
                                         int ltid, int ke, int b2, ull* acc, int barid) {
    float4 r[8];
    stage_ld8(r, ht, t, 0, ltid);
    stage_st8(h0, r, ltid);
    BARH(barid);
#pragma unroll 1
    for (int c = 0; c < 8; ++c) {
        const float* cur = (c & 1) ? h1b : h0;
        float* nxt = (c & 1) ? h0 : h1b;
        if (c < 7) stage_ld8(r, ht, t, c + 1, ltid);
        compute_chunk128(cur, Us, c, ke, b2, acc);
        if (c < 7) stage_st8(nxt, r, ltid);
        BARH(barid);
    }
}

// SMEM floats: U 2x8192 | hbuf 2x(2x4096) | zs 2x1280 | scr 2x8448 | shs 2x256
#define FB_U    0
#define FB_HBUF 16384
#define FB_ZS   32768
#define FB_SCR  35328
#define FB_SHS  52224
#define SMEM_FB (52736 * 4)

__global__ __launch_bounds__(256) void lstmfb_kernel(
    const float* __restrict__ Uf, const float* __restrict__ Ub)
{
    extern __shared__ float sm[];
    const int tid = threadIdx.x;
    const int half = tid >> 7;          // 0 = fwd, 1 = bwd
    const int ltid = tid & 127;
    const int barid = 1 + half;

    float* Us  = sm + FB_U    + half * 8192;
    float* h0  = sm + FB_HBUF + half * 8192;
    float* h1b = h0 + 4096;
    float* zs  = sm + FB_ZS   + half * 1280;
    float* scr = sm + FB_SCR  + half * 8448;
    float* shs = sm + FB_SHS  + half * 256;

    const float* U      = half ? Ub : Uf;
    const float* xw     = half ? g_xwb : g_xwf;
    float* h_btu        = half ? g_hb : g_hf;
    float* h_tub        = half ? g_hbt : g_hft;
    unsigned* bar       = half ? &g_barb : &g_barf;

    const int u0 = blockIdx.x << 2;
    const int ke = ltid >> 5, b2 = ltid & 31;
    const int gb = ltid & 63, gu2 = ltid >> 6;   // 2 units per thread

    load_U_shared(Us, U, u0, ltid, 128);
    __syncthreads();   // once; both halves aligned here

    float c0 = 0.f, c1 = 0.f;
    for (int s = 0; s < NT; ++s) {
        const int t = half ? (NT - 1 - s) : s;
        // zs prefetch (2 float4/thread) — overlaps barrier spin
#pragma unroll
        for (int j = 0; j < 2; ++j) {
            int f = ltid * 2 + j;
            int bb = f >> 2, g = f & 3;
            float4 xv = *(const float4*)&xw[((size_t)bb * NT + t) * NG + (size_t)g * ND + u0];
            *(float4*)&zs[bb * 20 + (g << 2)] = xv;
        }

        ull acc16[16];
#pragma unroll
        for (int i = 0; i < 16; ++i) acc16[i] = 0ull;

        if (s > 0) {
            half_grid_barrier(bar, (unsigned)s * NCTA, ltid, barid);
            const int tprev = half ? (t + 1) : (t - 1);
            accum128(h_tub, tprev, Us, h0, h1b, ltid, ke, b2, acc16, barid);
        } else {
            BARH(barid);
        }

        // ---- gate: 4-way k reduction, 2 units per thread ----
        {
            ull* scr_u = (ull*)scr;
#pragma unroll
            for (int bb = 0; bb < 2; ++bb)
#pragma unroll
                for (int u = 0; u < 4; ++u)
#pragma unroll
                    for (int p = 0; p < 2; ++p)
                        scr_u[(size_t)(((b2 << 1) | bb) * 66 + (ke << 4) + (u << 1) + p)] =
                            acc16[(bb * 4 + u) * 2 + p];
            BARH(barid);

            float hval[2];
#pragma unroll
            for (int j = 0; j < 2; ++j) {
                int uu = gu2 * 2 + j;
                float4 z = make_float4(0.f, 0.f, 0.f, 0.f);
#pragma unroll
                for (int k = 0; k < 4; ++k) {
                    float4 part = *(const float4*)&scr[gb * 132 + (k << 5) + (uu << 2)];
                    z.x += part.x; z.y += part.y; z.z += part.z; z.w += part.w;
                }
                float zi = z.x + zs[gb * 20 + uu];
                float zf = z.y + zs[gb * 20 + 4 + uu];
                float zg = z.z + zs[gb * 20 + 8 + uu];
                float zo = z.w + zs[gb * 20 + 12 + uu];
                float& cc = j ? c1 : c0;
                cc = fmaf(sigm(zf), cc, sigm(zi) * fmaxf(zg, 0.f));
                hval[j] = sigm(zo) * fmaxf(cc, 0.f);
                h_tub[((size_t)t * ND + u0 + uu) * NB + gb] = hval[j];
                shs[(gb << 2) + uu] = hval[j];
            }
            BARH(barid);
            if (ltid < 64) {
                float4 h4 = *(const float4*)&shs[ltid << 2];
                *(float4*)&h_btu[((size_t)ltid * NT + t) * ND + u0] = h4;
            }
        }
        BARH(barid);
    }
}

// ---------------- LayerNorm + residual ----------------
__global__ __launch_bounds__(256) void ln_kernel(
    const float* __restrict__ x, const float* __restrict__ gamma,
    const float* __restrict__ beta, float* __restrict__ out)
{
    __shared__ float red[16];
    __shared__ float s_mu, s_rs;
    const int r = blockIdx.x;
    const int tid = threadIdx.x;

    float4 v;
    if (tid < 128) v = *(const float4*)&g_hf[(size_t)r * ND + (tid << 2)];
    else           v = *(const float4*)&g_hb[(size_t)r * ND + ((tid - 128) << 2)];

    float s = v.x + v.y + v.z + v.w;
    float q = v.x * v.x + v.y * v.y + v.z * v.z + v.w * v.w;
#pragma unroll
    for (int o = 16; o; o >>= 1) {
        s += __shfl_down_sync(0xffffffffu, s, o);
        q += __shfl_down_sync(0xffffffffu, q, o);
    }
    if ((tid & 31) == 0) { red[tid >> 5] = s; red[8 + (tid >> 5)] = q; }
    __syncthreads();
    if (tid == 0) {
        float S = 0.f, Q = 0.f;
#pragma unroll
        for (int i = 0; i < 8; ++i) { S += red[i]; Q += red[8 + i]; }
        float mu = S * (1.f / 1024.f);
        float var = Q * (1.f / 1024.f) - mu * mu;
        s_mu = mu;
        s_rs = rsqrtf(var + 1e-6f);
    }
    __syncthreads();
    float mu = s_mu, rs = s_rs;
    int col = tid << 2;
    float4 g4 = *(const float4*)&gamma[col];
    float4 b4 = *(const float4*)&beta[col];
    float4 xv = *(const float4*)&x[(size_t)r * NI + col];
    float4 o;
    o.x = xv.x + (v.x - mu) * rs * g4.x + b4.x;
    o.y = xv.y + (v.y - mu) * rs * g4.y + b4.y;
    o.z = xv.z + (v.z - mu) * rs * g4.z + b4.z;
    o.w = xv.w + (v.w - mu) * rs * g4.w + b4.w;
    *(float4*)&out[(size_t)r * NI + col] = o;
}

// ---------------- host launch ----------------
extern "C" void kernel_launch(void* const* d_in, const int* in_sizes, int n_in,
                              void* d_out, int out_size)
{
    const float* x     = (const float*)d_in[0];
    const float* W1    = (const float*)d_in[1];
    const float* U1    = (const float*)d_in[2];
    const float* b1    = (const float*)d_in[3];
    const float* Wf    = (const float*)d_in[4];
    const float* Uf    = (const float*)d_in[5];
    const float* bf    = (const float*)d_in[6];
    const float* Wb    = (const float*)d_in[7];
    const float* Ub    = (const float*)d_in[8];
    const float* bb    = (const float*)d_in[9];
    const float* gamma = (const float*)d_in[10];
    const float* beta  = (const float*)d_in[11];
    float* out = (float*)d_out;

    void *p_xw1, *p_xwf, *p_xwb, *p_h1, *p_Wt1, *p_Wtf, *p_Wtb;
    void *p_Ah, *p_Al, *p_Bh1, *p_Bl1, *p_Bhf, *p_Blf, *p_Bhb, *p_Blb;
    cudaGetSymbolAddress(&p_xw1, g_xw1);
    cudaGetSymbolAddress(&p_xwf, g_xwf);
    cudaGetSymbolAddress(&p_xwb, g_xwb);
    cudaGetSymbolAddress(&p_h1,  g_h1);
    cudaGetSymbolAddress(&p_Wt1, g_Wt1);
    cudaGetSymbolAddress(&p_Wtf, g_Wtf);
    cudaGetSymbolAddress(&p_Wtb, g_Wtb);
    cudaGetSymbolAddress(&p_Ah,  g_Ah);
    cudaGetSymbolAddress(&p_Al,  g_Al);
    cudaGetSymbolAddress(&p_Bh1, g_Bh1);
    cudaGetSymbolAddress(&p_Bl1, g_Bl1);
    cudaGetSymbolAddress(&p_Bhf, g_Bhf);
    cudaGetSymbolAddress(&p_Blf, g_Blf);
    cudaGetSymbolAddress(&p_Bhb, g_Bhb);
    cudaGetSymbolAddress(&p_Blb, g_Blb);

    cudaFuncSetAttribute(lstm1_kernel,  cudaFuncAttributeMaxDynamicSharedMemorySize, SMEM_L1);
    cudaFuncSetAttribute(lstmfb_kernel, cudaFuncAttributeMaxDynamicSharedMemorySize, SMEM_FB);
    cudaFuncSetAttribute(gemm_fp16_kernel, cudaFuncAttributeMaxDynamicSharedMemorySize, SMEM_GEMM);

    const int M = NB * NT;
    dim3 gg(NG / 128, M / 128);

    reset_bars_kernel<<<1, 1>>>();
    transpose_kernel<<<dim3(NG / 32, NI / 32), 256>>>(W1, (float*)p_Wt1, NI, NG);
    transpose_kernel<<<dim3(NG / 32, ND / 32), 256>>>(Wf, (float*)p_Wtf, ND, NG);
    transpose_kernel<<<dim3(NG / 32, ND / 32), 256>>>(Wb, (float*)p_Wtb, ND, NG);

    {
        int n4 = NG * NI / 4;
        split_fp16_kernel<<<(n4 + 255) / 256, 256>>>((const float*)p_Wt1, (uint*)p_Bh1, (uint*)p_Bl1, n4);
        n4 = NG * ND / 4;
        split_fp16_kernel<<<(n4 + 255) / 256, 256>>>((const float*)p_Wtf, (uint*)p_Bhf, (uint*)p_Blf, n4);
        split_fp16_kernel<<<(n4 + 255) / 256, 256>>>((const float*)p_Wtb, (uint*)p_Bhb, (uint*)p_Blb, n4);
        n4 = M * NI / 4;
        split_fp16_kernel<<<(n4 + 255) / 256, 256>>>(x, (uint*)p_Ah, (uint*)p_Al, n4);
    }

    gemm_fp16_kernel<<<gg, 256, SMEM_GEMM>>>((const uint*)p_Ah, (const uint*)p_Al,
                                             (const uint*)p_Bh1, (const uint*)p_Bl1,
                                             b1, (float*)p_xw1, NI / 2);
    lstm1_kernel<<<NCTA, 256, SMEM_L1>>>(U1);

    {
        int n4 = M * ND / 4;
        split_fp16_kernel<<<(n4 + 255) / 256, 256>>>((const float*)p_h1, (uint*)p_Ah, (uint*)p_Al, n4);
    }
    gemm_fp16_kernel<<<gg, 256, SMEM_GEMM>>>((const uint*)p_Ah, (const uint*)p_Al,
                                             (const uint*)p_Bhf, (const uint*)p_Blf,
                                             bf, (float*)p_xwf, ND / 2);
    gemm_fp16_kernel<<<gg, 256, SMEM_GEMM>>>((const uint*)p_Ah, (const uint*)p_Al,
                                             (const uint*)p_Bhb, (const uint*)p_Blb,
                                             bb, (float*)p_xwb, ND / 2);
    lstmfb_kernel<<<NCTA, 256, SMEM_FB>>>(Uf, Ub);
    ln_kernel<<<M, 256>>>(x, gamma, beta, out);
}

// round 13
// speedup vs baseline: 1.1581x; 1.0391x over previous
#include <cuda_runtime.h>
#include <cuda_fp16.h>
#include <cstdint>

#define NB 64
#define NT 512
#define ND 512
#define NI 1024
#define NG 2048
#define NCTA 128

typedef unsigned long long ull;
typedef unsigned uint;

// ---------------- static device scratch ----------------
__device__ __align__(16) float g_xw1[(size_t)NB * NT * NG];
__device__ __align__(16) float g_xwf[(size_t)NB * NT * NG];
__device__ __align__(16) float g_xwb[(size_t)NB * NT * NG];
__device__ __align__(16) float g_h1 [(size_t)NB * NT * ND];   // [b][t][u]
__device__ __align__(16) float g_hf [(size_t)NB * NT * ND];
__device__ __align__(16) float g_hb [(size_t)NB * NT * ND];
__device__ __align__(16) float g_h1t[(size_t)NT * ND * NB];   // [t][u][b]
__device__ __align__(16) float g_hft[(size_t)NT * ND * NB];
__device__ __align__(16) float g_hbt[(size_t)NT * ND * NB];
__device__ __align__(16) float g_Wt1[(size_t)NG * NI];
__device__ __align__(16) float g_Wtf[(size_t)NG * ND];
__device__ __align__(16) float g_Wtb[(size_t)NG * ND];
// fp16 split GEMM operands
__device__ __align__(16) uint g_Ah [(size_t)NB * NT * NI / 2];
__device__ __align__(16) uint g_Al [(size_t)NB * NT * NI / 2];
__device__ __align__(16) uint g_Bh1[(size_t)NG * NI / 2];
__device__ __align__(16) uint g_Bl1[(size_t)NG * NI / 2];
__device__ __align__(16) uint g_Bhf[(size_t)NG * ND / 2];
__device__ __align__(16) uint g_Blf[(size_t)NG * ND / 2];
__device__ __align__(16) uint g_Bhb[(size_t)NG * ND / 2];
__device__ __align__(16) uint g_Blb[(size_t)NG * ND / 2];
__device__ unsigned g_bar1;
__device__ unsigned g_bar2;

// ---------------- packed f32x2 helpers ----------------
__device__ __forceinline__ ull pack2(float lo, float hi) {
    ull v; asm("mov.b64 %0, {%1, %2};" : "=l"(v) : "f"(lo), "f"(hi)); return v;
}
__device__ __forceinline__ void ffma2(ull& c, ull a, ull b) {
    asm("fma.rn.f32x2 %0, %1, %2, %0;" : "+l"(c) : "l"(a), "l"(b));
}
__device__ __forceinline__ float sigm(float z) { return 1.f / (1.f + __expf(-z)); }
__device__ __forceinline__ uint pack16(float a, float b) {
    __half2 h = __floats2half2_rn(a, b); return *(uint*)&h;
}
__device__ __forceinline__ float res16(float a) {
    return a - __half2float(__float2half_rn(a));
}

// ---------------- split grid barrier: early arrive, late wait ----------------
__device__ __forceinline__ void bar_arrive(unsigned* bar) {
    __threadfence();
    __syncthreads();
    if (threadIdx.x == 0) atomicAdd(bar, 1u);
}
__device__ __forceinline__ void bar_wait(unsigned* bar, unsigned target) {
    if (threadIdx.x == 0) {
        while (*((volatile unsigned*)bar) < target) __nanosleep(32);
        __threadfence();
    }
    __syncthreads();
}

__global__ void reset_bars_kernel() { g_bar1 = 0u; g_bar2 = 0u; }

// ---------------- fp16 split: v -> hi + lo (packed pairs) ----------------
__global__ __launch_bounds__(256) void split_fp16_kernel(
    const float* __restrict__ src, uint* __restrict__ hi, uint* __restrict__ lo, int n4)
{
    int i = blockIdx.x * 256 + threadIdx.x;
    if (i >= n4) return;
    float4 v = ((const float4*)src)[i];
    uint2 ho, lo2;
    ho.x = pack16(v.x, v.y); ho.y = pack16(v.z, v.w);
    lo2.x = pack16(res16(v.x), res16(v.y));
    lo2.y = pack16(res16(v.z), res16(v.w));
    ((uint2*)hi)[i] = ho;
    ((uint2*)lo)[i] = lo2;
}

// ================= fp16 mma GEMM (R7 passing version, unchanged) =================
#define KST 12
#define GARRU (128 * KST)
#define GBUFU (4 * GARRU)
#define SMEM_GEMM (2 * GBUFU * 4)

__device__ __forceinline__ void mma_f16(float* d, const uint* a, const uint* b) {
    asm volatile(
        "mma.sync.aligned.m16n8k16.row.col.f32.f16.f16.f32 "
        "{%0,%1,%2,%3}, {%4,%5,%6,%7}, {%8,%9}, {%0,%1,%2,%3};"
        : "+f"(d[0]), "+f"(d[1]), "+f"(d[2]), "+f"(d[3])
        : "r"(a[0]), "r"(a[1]), "r"(a[2]), "r"(a[3]), "r"(b[0]), "r"(b[1]));
}

__global__ __launch_bounds__(256, 1) void gemm_fp16_kernel(
    const uint* __restrict__ Ah, const uint* __restrict__ Al,
    const uint* __restrict__ Bh, const uint* __restrict__ Bl,
    const float* __restrict__ bias, float* __restrict__ C, int K2)
{
    extern __shared__ uint sgu[];
    const int tid = threadIdx.x;
    const int wid = tid >> 5, lane = tid & 31;
    const int lr = lane >> 2, lc = lane & 3;
    const int warp_m = wid & 3, warp_n = wid >> 2;
    const int n0 = blockIdx.x * 128, m0 = blockIdx.y * 128;

    const int row_s = tid >> 1, half = tid & 1;
    const size_t aoff = (size_t)(m0 + row_s) * K2 + half * 4;
    const size_t boff = (size_t)(n0 + row_s) * K2 + half * 4;
    const uint sidx = row_s * KST + half * 4;

    float acc[2][8][4];
#pragma unroll
    for (int mt = 0; mt < 2; ++mt)
#pragma unroll
        for (int nt = 0; nt < 8; ++nt)
#pragma unroll
            for (int q = 0; q < 4; ++q) acc[mt][nt][q] = 0.f;

    const int nc = K2 >> 3;
    uint4 rAh, rAl, rBh, rBl;
    rAh = *(const uint4*)&Ah[aoff];
    rAl = *(const uint4*)&Al[aoff];
    rBh = *(const uint4*)&Bh[boff];
    rBl = *(const uint4*)&Bl[boff];
    *(uint4*)&sgu[0 * GARRU + sidx] = rAh;
    *(uint4*)&sgu[1 * GARRU + sidx] = rAl;
    *(uint4*)&sgu[2 * GARRU + sidx] = rBh;
    *(uint4*)&sgu[3 * GARRU + sidx] = rBl;
    __syncthreads();

#pragma unroll 1
    for (int c = 0; c < nc; ++c) {
        const int buf = c & 1;
        if (c + 1 < nc) {
            rAh = *(const uint4*)&Ah[aoff + (c + 1) * 8];
            rAl = *(const uint4*)&Al[aoff + (c + 1) * 8];
            rBh = *(const uint4*)&Bh[boff + (c + 1) * 8];
            rBl = *(const uint4*)&Bl[boff + (c + 1) * 8];
        }
        const uint* sAh = sgu + buf * GBUFU + 0 * GARRU;
        const uint* sAl = sgu + buf * GBUFU + 1 * GARRU;
        const uint* sBh = sgu + buf * GBUFU + 2 * GARRU;
        const uint* sBl = sgu + buf * GBUFU + 3 * GARRU;

        uint ah[2][4], al[2][4];
#pragma unroll
        for (int mt = 0; mt < 2; ++mt) {
            int row = warp_m * 32 + mt * 16 + lr;
            ah[mt][0] = sAh[row * KST + lc];
            ah[mt][1] = sAh[(row + 8) * KST + lc];
            ah[mt][2] = sAh[row * KST + lc + 4];
            ah[mt][3] = sAh[(row + 8) * KST + lc + 4];
            al[mt][0] = sAl[row * KST + lc];
            al[mt][1] = sAl[(row + 8) * KST + lc];
            al[mt][2] = sAl[row * KST + lc + 4];
            al[mt][3] = sAl[(row + 8) * KST + lc + 4];
        }
        uint bh[8][2], bl[8][2];
#pragma unroll
        for (int nt = 0; nt < 8; ++nt) {
            int n = warp_n * 64 + nt * 8 + lr;
            bh[nt][0] = sBh[n * KST + lc];
            bh[nt][1] = sBh[n * KST + lc + 4];
            bl[nt][0] = sBl[n * KST + lc];
            bl[nt][1] = sBl[n * KST + lc + 4];
        }
#pragma unroll
        for (int mt = 0; mt < 2; ++mt)
#pragma unroll
            for (int nt = 0; nt < 8; ++nt) {
                mma_f16(acc[mt][nt], ah[mt], bh[nt]);
                mma_f16(acc[mt][nt], al[mt], bh[nt]);
                mma_f16(acc[mt][nt], ah[mt], bl[nt]);
            }

        if (c + 1 < nc) {
            const int nb = (c + 1) & 1;
            *(uint4*)&sgu[nb * GBUFU + 0 * GARRU + sidx] = rAh;
            *(uint4*)&sgu[nb * GBUFU + 1 * GARRU + sidx] = rAl;
            *(uint4*)&sgu[nb * GBUFU + 2 * GARRU + sidx] = rBh;
            *(uint4*)&sgu[nb * GBUFU + 3 * GARRU + sidx] = rBl;
        }
        __syncthreads();
    }

#pragma unroll
    for (int mt = 0; mt < 2; ++mt) {
        int row = m0 + warp_m * 32 + mt * 16 + lr;
#pragma unroll
        for (int nt = 0; nt < 8; ++nt) {
            int col = n0 + warp_n * 64 + nt * 8 + 2 * lc;
            float2 bv = *(const float2*)&bias[col];
            float2 o0 = make_float2(acc[mt][nt][0] + bv.x, acc[mt][nt][1] + bv.y);
            float2 o1 = make_float2(acc[mt][nt][2] + bv.x, acc[mt][nt][3] + bv.y);
            *(float2*)&C[(size_t)row * NG + col] = o0;
            *(float2*)&C[(size_t)(row + 8) * NG + col] = o1;
        }
    }
}

// ---------------- weight transpose ----------------
__global__ __launch_bounds__(256) void transpose_kernel(
    const float* __restrict__ W, float* __restrict__ Wt, int K, int N)
{
    __shared__ float t[32][33];
    const int tx = threadIdx.x & 31, ty = threadIdx.x >> 5;
    const int n0 = blockIdx.x << 5, k0 = blockIdx.y << 5;
#pragma unroll
    for (int i = 0; i < 32; i += 8)
        t[ty + i][tx] = W[(size_t)(k0 + ty + i) * N + n0 + tx];
    __syncthreads();
#pragma unroll
    for (int i = 0; i < 32; i += 8)
        Wt[(size_t)(n0 + ty + i) * K + k0 + tx] = t[tx][ty + i];
}

// ================= LSTM recurrence: direct-LDG accum, sync-free =================
__device__ __forceinline__ void load_U_shared(float* Us, const float* __restrict__ U,
                                              int u0, int tid) {
    for (int idx = tid; idx < 8192; idx += 256) {
        int k = idx >> 4, r = idx & 15;
        int u = r >> 2, g = r & 3;
        Us[idx] = U[(size_t)k * NG + (size_t)g * ND + u0 + u];
    }
}

// h[t][k][b]: thread (ke, b2) reads its 2 batches directly from global, no SMEM.
// k-order identical to the staged version -> bit-identical accumulation.
__device__ __forceinline__ void accum_direct(const float* __restrict__ ht, int t,
                                             const float* Us, int ke, int b2, ull* acc)
{
    const float* base = ht + (size_t)t * (ND * NB) + (b2 << 1);
    float2 cur[8], nxt[8];
#pragma unroll
    for (int ii = 0; ii < 8; ++ii)
        cur[ii] = *(const float2*)&base[(size_t)(ii * 8 + ke) * NB];
#pragma unroll 1
    for (int c = 0; c < 8; ++c) {
        if (c < 7) {
#pragma unroll
            for (int ii = 0; ii < 8; ++ii)
                nxt[ii] = *(const float2*)&base[(size_t)((c + 1) * 64 + ii * 8 + ke) * NB];
        }
#pragma unroll
        for (int ii = 0; ii < 8; ++ii) {
            int k = (c << 6) + ii * 8 + ke;
            ull a0 = pack2(cur[ii].x, cur[ii].x);
            ull a1 = pack2(cur[ii].y, cur[ii].y);
            const ulonglong2* uvp = (const ulonglong2*)&Us[(size_t)k << 4];
#pragma unroll
            for (int u = 0; u < 4; ++u) {
                ulonglong2 uv = uvp[u];
                ffma2(acc[(0 * 4 + u) * 2 + 0], a0, uv.x);
                ffma2(acc[(0 * 4 + u) * 2 + 1], a0, uv.y);
                ffma2(acc[(1 * 4 + u) * 2 + 0], a1, uv.x);
                ffma2(acc[(1 * 4 + u) * 2 + 1], a1, uv.y);
            }
        }
#pragma unroll
        for (int ii = 0; ii < 8; ++ii) cur[ii] = nxt[ii];
    }
}

__device__ __forceinline__ void stage_zs(float* zs, const float* __restrict__ xw,
                                         int t, int u0, int tid) {
    int bb = tid >> 2, g = tid & 3;
    float4 xv = *(const float4*)&xw[((size_t)bb * NT + t) * NG + (size_t)g * ND + u0];
    *(float4*)&zs[bb * 20 + (g << 2)] = xv;
}

__device__ __forceinline__ void gate(float* __restrict__ h_btu, float* __restrict__ h_tub,
                                     int t, int u0, const ull* acc, float& cst,
                                     const float* zs, float* scr, float* shs,
                                     int tid, int ke, int b2, int gb, int gu) {
    ull* scr_u = (ull*)scr;
#pragma unroll
    for (int bb = 0; bb < 2; ++bb)
#pragma unroll
        for (int u = 0; u < 4; ++u)
#pragma unroll
            for (int p = 0; p < 2; ++p)
                scr_u[(size_t)(((b2 << 1) | bb) * 66 + (ke << 3) + (u << 1) + p)] =
                    acc[(bb * 4 + u) * 2 + p];
    __syncthreads();

    float4 z = make_float4(0.f, 0.f, 0.f, 0.f);
#pragma unroll
    for (int k = 0; k < 8; ++k) {
        float4 part = *(const float4*)&scr[gb * 132 + (k << 4) + (gu << 2)];
        z.x += part.x; z.y += part.y; z.z += part.z; z.w += part.w;
    }
    float zi = z.x + zs[gb * 20 + gu];
    float zf = z.y + zs[gb * 20 + 4 + gu];
    float zg = z.z + zs[gb * 20 + 8 + gu];
    float zo = z.w + zs[gb * 20 + 12 + gu];
    float ig = sigm(zi), fg = sigm(zf);
    float gv = fmaxf(zg, 0.f), og = sigm(zo);
    cst = fmaf(fg, cst, ig * gv);
    float h = og * fmaxf(cst, 0.f);

    h_tub[((size_t)t * ND + u0 + gu) * NB + gb] = h;
    shs[(gb << 2) + gu] = h;
    __syncthreads();
    if (tid < 64) {
        float4 h4 = *(const float4*)&shs[tid << 2];
        *(float4*)&h_btu[((size_t)tid * NT + t) * ND + u0] = h4;
    }
}

// smem floats: Us 8192 | zs 1280 | scr 8448 | shs 256 = 18176
#define SMEM_L1 (18176 * 4)

__global__ __launch_bounds__(256) void lstm1_kernel(const float* __restrict__ U)
{
    extern __shared__ float sm[];
    float* Us  = sm;
    float* zs  = sm + 8192;
    float* scr = sm + 9472;
    float* shs = sm + 17920;

    const int tid = threadIdx.x;
    const int ke = tid >> 5, b2 = tid & 31;
    const int gb = tid & 63, gu = tid >> 6;
    const int u0 = blockIdx.x << 2;

    load_U_shared(Us, U, u0, tid);
    __syncthreads();

    float cst = 0.f;
    for (int t = 0; t < NT; ++t) {
        if (t > 0) bar_arrive(&g_bar1);          // h[t-1] published; overlap zs fetch
        stage_zs(zs, g_xw1, t, u0, tid);
        ull acc16[16];
#pragma unroll
        for (int i = 0; i < 16; ++i) acc16[i] = 0ull;
        if (t > 0) {
            bar_wait(&g_bar1, (unsigned)t * NCTA);
            accum_direct(g_h1t, t - 1, Us, ke, b2, acc16);
        }
        gate(g_h1, g_h1t, t, u0, acc16, cst, zs, scr, shs, tid, ke, b2, gb, gu);
    }
}

// smem floats: Ufs 8192 | Ubs 8192 | zsf 1280 | zsb 1280 | scr 8448 | shs 256 = 27648
#define SMEM_FB (27648 * 4)

__global__ __launch_bounds__(256) void lstmfb_kernel(
    const float* __restrict__ Uf, const float* __restrict__ Ub)
{
    extern __shared__ float sm[];
    float* Ufs = sm;
    float* Ubs = sm + 8192;
    float* zsf = sm + 16384;
    float* zsb = sm + 17664;
    float* scr = sm + 18944;
    float* shs = sm + 27392;

    const int tid = threadIdx.x;
    const int ke = tid >> 5, b2 = tid & 31;
    const int gb = tid & 63, gu = tid >> 6;
    const int u0 = blockIdx.x << 2;

    load_U_shared(Ufs, Uf, u0, tid);
    load_U_shared(Ubs, Ub, u0, tid);
    __syncthreads();

    float cf = 0.f, cb = 0.f;
    for (int s = 0; s < NT; ++s) {
        int tf = s, tb = NT - 1 - s;
        if (s > 0) bar_arrive(&g_bar2);          // hf[s-1] & hb[N-s] published
        stage_zs(zsf, g_xwf, tf, u0, tid);
        stage_zs(zsb, g_xwb, tb, u0, tid);
        ull af[16], ab[16];
#pragma unroll
        for (int i = 0; i < 16; ++i) { af[i] = 0ull; ab[i] = 0ull; }
        if (s > 0) {
            bar_wait(&g_bar2, (unsigned)s * NCTA);
            accum_direct(g_hft, tf - 1, Ufs, ke, b2, af);
            gate(g_hf, g_hft, tf, u0, af, cf, zsf, scr, shs, tid, ke, b2, gb, gu);
            accum_direct(g_hbt, tb + 1, Ubs, ke, b2, ab);
            gate(g_hb, g_hbt, tb, u0, ab, cb, zsb, scr, shs, tid, ke, b2, gb, gu);
        } else {
            gate(g_hf, g_hft, tf, u0, af, cf, zsf, scr, shs, tid, ke, b2, gb, gu);
            gate(g_hb, g_hbt, tb, u0, ab, cb, zsb, scr, shs, tid, ke, b2, gb, gu);
        }
    }
}

// ---------------- LayerNorm + residual ----------------
__global__ __launch_bounds__(256) void ln_kernel(
    const float* __restrict__ x, const float* __restrict__ gamma,
    const float* __restrict__ beta, float* __restrict__ out)
{
    __shared__ float red[16];
    __shared__ float s_mu, s_rs;
    const int r = blockIdx.x;
    const int tid = threadIdx.x;

    float4 v;
    if (tid < 128) v = *(const float4*)&g_hf[(size_t)r * ND + (tid << 2)];
    else           v = *(const float4*)&g_hb[(size_t)r * ND + ((tid - 128) << 2)];

    float s = v.x + v.y + v.z + v.w;
    float q = v.x * v.x + v.y * v.y + v.z * v.z + v.w * v.w;
#pragma unroll
    for (int o = 16; o; o >>= 1) {
        s += __shfl_down_sync(0xffffffffu, s, o);
        q += __shfl_down_sync(0xffffffffu, q, o);
    }
    if ((tid & 31) == 0) { red[tid >> 5] = s; red[8 + (tid >> 5)] = q; }
    __syncthreads();
    if (tid == 0) {
        float S = 0.f, Q = 0.f;
#pragma unroll
        for (int i = 0; i < 8; ++i) { S += red[i]; Q += red[8 + i]; }
        float mu = S * (1.f / 1024.f);
        float var = Q * (1.f / 1024.f) - mu * mu;
        s_mu = mu;
        s_rs = rsqrtf(var + 1e-6f);
    }
    __syncthreads();
    float mu = s_mu, rs = s_rs;
    int col = tid << 2;
    float4 g4 = *(const float4*)&gamma[col];
    float4 b4 = *(const float4*)&beta[col];
    float4 xv = *(const float4*)&x[(size_t)r * NI + col];
    float4 o;
    o.x = xv.x + (v.x - mu) * rs * g4.x + b4.x;
    o.y = xv.y + (v.y - mu) * rs * g4.y + b4.y;
    o.z = xv.z + (v.z - mu) * rs * g4.z + b4.z;
    o.w = xv.w + (v.w - mu) * rs * g4.w + b4.w;
    *(float4*)&out[(size_t)r * NI + col] = o;
}

// ---------------- host launch ----------------
extern "C" void kernel_launch(void* const* d_in, const int* in_sizes, int n_in,
                              void* d_out, int out_size)
{
    const float* x     = (const float*)d_in[0];
    const float* W1    = (const float*)d_in[1];
    const float* U1    = (const float*)d_in[2];
    const float* b1    = (const float*)d_in[3];
    const float* Wf    = (const float*)d_in[4];
    const float* Uf    = (const float*)d_in[5];
    const float* bf    = (const float*)d_in[6];
    const float* Wb    = (const float*)d_in[7];
    const float* Ub    = (const float*)d_in[8];
    const float* bb    = (const float*)d_in[9];
    const float* gamma = (const float*)d_in[10];
    const float* beta  = (const float*)d_in[11];
    float* out = (float*)d_out;

    void *p_xw1, *p_xwf, *p_xwb, *p_h1, *p_Wt1, *p_Wtf, *p_Wtb;
    void *p_Ah, *p_Al, *p_Bh1, *p_Bl1, *p_Bhf, *p_Blf, *p_Bhb, *p_Blb;
    cudaGetSymbolAddress(&p_xw1, g_xw1);
    cudaGetSymbolAddress(&p_xwf, g_xwf);
    cudaGetSymbolAddress(&p_xwb, g_xwb);
    cudaGetSymbolAddress(&p_h1,  g_h1);
    cudaGetSymbolAddress(&p_Wt1, g_Wt1);
    cudaGetSymbolAddress(&p_Wtf, g_Wtf);
    cudaGetSymbolAddress(&p_Wtb, g_Wtb);
    cudaGetSymbolAddress(&p_Ah,  g_Ah);
    cudaGetSymbolAddress(&p_Al,  g_Al);
    cudaGetSymbolAddress(&p_Bh1, g_Bh1);
    cudaGetSymbolAddress(&p_Bl1, g_Bl1);
    cudaGetSymbolAddress(&p_Bhf, g_Bhf);
    cudaGetSymbolAddress(&p_Blf, g_Blf);
    cudaGetSymbolAddress(&p_Bhb, g_Bhb);
    cudaGetSymbolAddress(&p_Blb, g_Blb);

    cudaFuncSetAttribute(lstm1_kernel,  cudaFuncAttributeMaxDynamicSharedMemorySize, SMEM_L1);
    cudaFuncSetAttribute(lstmfb_kernel, cudaFuncAttributeMaxDynamicSharedMemorySize, SMEM_FB);
    cudaFuncSetAttribute(gemm_fp16_kernel, cudaFuncAttributeMaxDynamicSharedMemorySize, SMEM_GEMM);

    const int M = NB * NT;
    dim3 gg(NG / 128, M / 128);

    reset_bars_kernel<<<1, 1>>>();
    transpose_kernel<<<dim3(NG / 32, NI / 32), 256>>>(W1, (float*)p_Wt1, NI, NG);
    transpose_kernel<<<dim3(NG / 32, ND / 32), 256>>>(Wf, (float*)p_Wtf, ND, NG);
    transpose_kernel<<<dim3(NG / 32, ND / 32), 256>>>(Wb, (float*)p_Wtb, ND, NG);

    {
        int n4 = NG * NI / 4;
        split_fp16_kernel<<<(n4 + 255) / 256, 256>>>((const float*)p_Wt1, (uint*)p_Bh1, (uint*)p_Bl1, n4);
        n4 = NG * ND / 4;
        split_fp16_kernel<<<(n4 + 255) / 256, 256>>>((const float*)p_Wtf, (uint*)p_Bhf, (uint*)p_Blf, n4);
        split_fp16_kernel<<<(n4 + 255) / 256, 256>>>((const float*)p_Wtb, (uint*)p_Bhb, (uint*)p_Blb, n4);
        n4 = M * NI / 4;
        split_fp16_kernel<<<(n4 + 255) / 256, 256>>>(x, (uint*)p_Ah, (uint*)p_Al, n4);
    }

    gemm_fp16_kernel<<<gg, 256, SMEM_GEMM>>>((const uint*)p_Ah, (const uint*)p_Al,
                                             (const uint*)p_Bh1, (const uint*)p_Bl1,
                                             b1, (float*)p_xw1, NI / 2);
    lstm1_kernel<<<NCTA, 256, SMEM_L1>>>(U1);

    {
        int n4 = M * ND / 4;
        split_fp16_kernel<<<(n4 + 255) / 256, 256>>>((const float*)p_h1, (uint*)p_Ah, (uint*)p_Al, n4);
    }
    gemm_fp16_kernel<<<gg, 256, SMEM_GEMM>>>((const uint*)p_Ah, (const uint*)p_Al,
                                             (const uint*)p_Bhf, (const uint*)p_Blf,
                                             bf, (float*)p_xwf, ND / 2);
    gemm_fp16_kernel<<<gg, 256, SMEM_GEMM>>>((const uint*)p_Ah, (const uint*)p_Al,
                                             (const uint*)p_Bhb, (const uint*)p_Blb,
                                             bb, (float*)p_xwb, ND / 2);
    lstmfb_kernel<<<NCTA, 256, SMEM_FB>>>(Uf, Ub);
    ln_kernel<<<M, 256>>>(x, gamma, beta, out);
}

// round 14
// speedup vs baseline: 1.2843x; 1.1089x over previous
#include <cuda_runtime.h>
#include <cuda_fp16.h>
#include <cstdint>

#define NB 64
#define NT 512
#define ND 512
#define NI 1024
#define NG 2048
#define NCTA 128

typedef unsigned long long ull;
typedef unsigned uint;

// ---------------- static device scratch ----------------
__device__ __align__(16) float g_xw1[(size_t)NB * NT * NG];
__device__ __align__(16) float g_xwf[(size_t)NB * NT * NG];
__device__ __align__(16) float g_xwb[(size_t)NB * NT * NG];
__device__ __align__(16) float g_h1 [(size_t)NB * NT * ND];   // [b][t][u]
__device__ __align__(16) float g_hf [(size_t)NB * NT * ND];
__device__ __align__(16) float g_hb [(size_t)NB * NT * ND];
__device__ __align__(16) float g_h1t[(size_t)NT * ND * NB];   // [t][u][b]
__device__ __align__(16) float g_hft[(size_t)NT * ND * NB];
__device__ __align__(16) float g_hbt[(size_t)NT * ND * NB];
__device__ __align__(16) float g_Wt1[(size_t)NG * NI];
__device__ __align__(16) float g_Wtf[(size_t)NG * ND];
__device__ __align__(16) float g_Wtb[(size_t)NG * ND];
// fp16 split GEMM operands
__device__ __align__(16) uint g_Ah [(size_t)NB * NT * NI / 2];
__device__ __align__(16) uint g_Al [(size_t)NB * NT * NI / 2];
__device__ __align__(16) uint g_Bh1[(size_t)NG * NI / 2];
__device__ __align__(16) uint g_Bl1[(size_t)NG * NI / 2];
__device__ __align__(16) uint g_Bhf[(size_t)NG * ND / 2];
__device__ __align__(16) uint g_Blf[(size_t)NG * ND / 2];
__device__ __align__(16) uint g_Bhb[(size_t)NG * ND / 2];
__device__ __align__(16) uint g_Blb[(size_t)NG * ND / 2];
__device__ unsigned g_bar1;
__device__ unsigned g_bar2;

// ---------------- helpers ----------------
__device__ __forceinline__ ull pack2(float lo, float hi) {
    ull v; asm("mov.b64 %0, {%1, %2};" : "=l"(v) : "f"(lo), "f"(hi)); return v;
}
__device__ __forceinline__ void ffma2(ull& c, ull a, ull b) {
    asm("fma.rn.f32x2 %0, %1, %2, %0;" : "+l"(c) : "l"(a), "l"(b));
}
__device__ __forceinline__ float sigm(float z) { return 1.f / (1.f + __expf(-z)); }
__device__ __forceinline__ uint pack16(float a, float b) {
    __half2 h = __floats2half2_rn(a, b); return *(uint*)&h;
}
__device__ __forceinline__ float res16(float a) {
    return a - __half2float(__float2half_rn(a));
}

// ---------------- split grid barrier ----------------
__device__ __forceinline__ void bar_arrive(unsigned* bar) {
    __threadfence();
    __syncthreads();
    if (threadIdx.x == 0) atomicAdd(bar, 1u);
}
__device__ __forceinline__ void bar_wait(unsigned* bar, unsigned target) {
    if (threadIdx.x == 0) {
        while (*((volatile unsigned*)bar) < target) __nanosleep(32);
        __threadfence();
    }
    __syncthreads();
}

__global__ void reset_bars_kernel() { g_bar1 = 0u; g_bar2 = 0u; }

// ---------------- fp16 split ----------------
__global__ __launch_bounds__(256) void split_fp16_kernel(
    const float* __restrict__ src, uint* __restrict__ hi, uint* __restrict__ lo, int n4)
{
    int i = blockIdx.x * 256 + threadIdx.x;
    if (i >= n4) return;
    float4 v = ((const float4*)src)[i];
    uint2 ho, lo2;
    ho.x = pack16(v.x, v.y); ho.y = pack16(v.z, v.w);
    lo2.x = pack16(res16(v.x), res16(v.y));
    lo2.y = pack16(res16(v.z), res16(v.w));
    ((uint2*)hi)[i] = ho;
    ((uint2*)lo)[i] = lo2;
}

// ================= fp16 mma GEMM (unchanged) =================
#define KST 12
#define GARRU (128 * KST)
#define GBUFU (4 * GARRU)
#define SMEM_GEMM (2 * GBUFU * 4)

__device__ __forceinline__ void mma_f16(float* d, const uint* a, const uint* b) {
    asm volatile(
        "mma.sync.aligned.m16n8k16.row.col.f32.f16.f16.f32 "
        "{%0,%1,%2,%3}, {%4,%5,%6,%7}, {%8,%9}, {%0,%1,%2,%3};"
        : "+f"(d[0]), "+f"(d[1]), "+f"(d[2]), "+f"(d[3])
        : "r"(a[0]), "r"(a[1]), "r"(a[2]), "r"(a[3]), "r"(b[0]), "r"(b[1]));
}

__global__ __launch_bounds__(256, 1) void gemm_fp16_kernel(
    const uint* __restrict__ Ah, const uint* __restrict__ Al,
    const uint* __restrict__ Bh, const uint* __restrict__ Bl,
    const float* __restrict__ bias, float* __restrict__ C, int K2)
{
    extern __shared__ uint sgu[];
    const int tid = threadIdx.x;
    const int wid = tid >> 5, lane = tid & 31;
    const int lr = lane >> 2, lc = lane & 3;
    const int warp_m = wid & 3, warp_n = wid >> 2;
    const int n0 = blockIdx.x * 128, m0 = blockIdx.y * 128;

    const int row_s = tid >> 1, half = tid & 1;
    const size_t aoff = (size_t)(m0 + row_s) * K2 + half * 4;
    const size_t boff = (size_t)(n0 + row_s) * K2 + half * 4;
    const uint sidx = row_s * KST + half * 4;

    float acc[2][8][4];
#pragma unroll
    for (int mt = 0; mt < 2; ++mt)
#pragma unroll
        for (int nt = 0; nt < 8; ++nt)
#pragma unroll
            for (int q = 0; q < 4; ++q) acc[mt][nt][q] = 0.f;

    const int nc = K2 >> 3;
    uint4 rAh, rAl, rBh, rBl;
    rAh = *(const uint4*)&Ah[aoff];
    rAl = *(const uint4*)&Al[aoff];
    rBh = *(const uint4*)&Bh[boff];
    rBl = *(const uint4*)&Bl[boff];
    *(uint4*)&sgu[0 * GARRU + sidx] = rAh;
    *(uint4*)&sgu[1 * GARRU + sidx] = rAl;
    *(uint4*)&sgu[2 * GARRU + sidx] = rBh;
    *(uint4*)&sgu[3 * GARRU + sidx] = rBl;
    __syncthreads();

#pragma unroll 1
    for (int c = 0; c < nc; ++c) {
        const int buf = c & 1;
        if (c + 1 < nc) {
            rAh = *(const uint4*)&Ah[aoff + (c + 1) * 8];
            rAl = *(const uint4*)&Al[aoff + (c + 1) * 8];
            rBh = *(const uint4*)&Bh[boff + (c + 1) * 8];
            rBl = *(const uint4*)&Bl[boff + (c + 1) * 8];
        }
        const uint* sAh = sgu + buf * GBUFU + 0 * GARRU;
        const uint* sAl = sgu + buf * GBUFU + 1 * GARRU;
        const uint* sBh = sgu + buf * GBUFU + 2 * GARRU;
        const uint* sBl = sgu + buf * GBUFU + 3 * GARRU;

        uint ah[2][4], al[2][4];
#pragma unroll
        for (int mt = 0; mt < 2; ++mt) {
            int row = warp_m * 32 + mt * 16 + lr;
            ah[mt][0] = sAh[row * KST + lc];
            ah[mt][1] = sAh[(row + 8) * KST + lc];
            ah[mt][2] = sAh[row * KST + lc + 4];
            ah[mt][3] = sAh[(row + 8) * KST + lc + 4];
            al[mt][0] = sAl[row * KST + lc];
            al[mt][1] = sAl[(row + 8) * KST + lc];
            al[mt][2] = sAl[row * KST + lc + 4];
            al[mt][3] = sAl[(row + 8) * KST + lc + 4];
        }
        uint bh[8][2], bl[8][2];
#pragma unroll
        for (int nt = 0; nt < 8; ++nt) {
            int n = warp_n * 64 + nt * 8 + lr;
            bh[nt][0] = sBh[n * KST + lc];
            bh[nt][1] = sBh[n * KST + lc + 4];
            bl[nt][0] = sBl[n * KST + lc];
            bl[nt][1] = sBl[n * KST + lc + 4];
        }
#pragma unroll
        for (int mt = 0; mt < 2; ++mt)
#pragma unroll
            for (int nt = 0; nt < 8; ++nt) {
                mma_f16(acc[mt][nt], ah[mt], bh[nt]);
                mma_f16(acc[mt][nt], al[mt], bh[nt]);
                mma_f16(acc[mt][nt], ah[mt], bl[nt]);
            }

        if (c + 1 < nc) {
            const int nb = (c + 1) & 1;
            *(uint4*)&sgu[nb * GBUFU + 0 * GARRU + sidx] = rAh;
            *(uint4*)&sgu[nb * GBUFU + 1 * GARRU + sidx] = rAl;
            *(uint4*)&sgu[nb * GBUFU + 2 * GARRU + sidx] = rBh;
            *(uint4*)&sgu[nb * GBUFU + 3 * GARRU + sidx] = rBl;
        }
        __syncthreads();
    }

#pragma unroll
    for (int mt = 0; mt < 2; ++mt) {
        int row = m0 + warp_m * 32 + mt * 16 + lr;
#pragma unroll
        for (int nt = 0; nt < 8; ++nt) {
            int col = n0 + warp_n * 64 + nt * 8 + 2 * lc;
            float2 bv = *(const float2*)&bias[col];
            float2 o0 = make_float2(acc[mt][nt][0] + bv.x, acc[mt][nt][1] + bv.y);
            float2 o1 = make_float2(acc[mt][nt][2] + bv.x, acc[mt][nt][3] + bv.y);
            *(float2*)&C[(size_t)row * NG + col] = o0;
            *(float2*)&C[(size_t)(row + 8) * NG + col] = o1;
        }
    }
}

// ---------------- weight transpose ----------------
__global__ __launch_bounds__(256) void transpose_kernel(
    const float* __restrict__ W, float* __restrict__ Wt, int K, int N)
{
    __shared__ float t[32][33];
    const int tx = threadIdx.x & 31, ty = threadIdx.x >> 5;
    const int n0 = blockIdx.x << 5, k0 = blockIdx.y << 5;
#pragma unroll
    for (int i = 0; i < 32; i += 8)
        t[ty + i][tx] = W[(size_t)(k0 + ty + i) * N + n0 + tx];
    __syncthreads();
#pragma unroll
    for (int i = 0; i < 32; i += 8)
        Wt[(size_t)(n0 + ty + i) * K + k0 + tx] = t[tx][ty + i];
}

// ================= LSTM recurrence =================
__device__ __forceinline__ void load_U_shared(float* Us, const float* __restrict__ U,
                                              int u0, int tid) {
    for (int idx = tid; idx < 8192; idx += 256) {
        int k = idx >> 4, r = idx & 15;
        int u = r >> 2, g = r & 3;
        Us[idx] = U[(size_t)k * NG + (size_t)g * ND + u0 + u];
    }
}

__device__ __forceinline__ void accum_direct(const float* __restrict__ ht, int t,
                                             const float* Us, int ke, int b2, ull* acc)
{
    const float* base = ht + (size_t)t * (ND * NB) + (b2 << 1);
    float2 cur[8], nxt[8];
#pragma unroll
    for (int ii = 0; ii < 8; ++ii)
        cur[ii] = *(const float2*)&base[(size_t)(ii * 8 + ke) * NB];
#pragma unroll 1
    for (int c = 0; c < 8; ++c) {
        if (c < 7) {
#pragma unroll
            for (int ii = 0; ii < 8; ++ii)
                nxt[ii] = *(const float2*)&base[(size_t)((c + 1) * 64 + ii * 8 + ke) * NB];
        }
#pragma unroll
        for (int ii = 0; ii < 8; ++ii) {
            int k = (c << 6) + ii * 8 + ke;
            ull a0 = pack2(cur[ii].x, cur[ii].x);
            ull a1 = pack2(cur[ii].y, cur[ii].y);
            const ulonglong2* uvp = (const ulonglong2*)&Us[(size_t)k << 4];
#pragma unroll
            for (int u = 0; u < 4; ++u) {
                ulonglong2 uv = uvp[u];
                ffma2(acc[(0 * 4 + u) * 2 + 0], a0, uv.x);
                ffma2(acc[(0 * 4 + u) * 2 + 1], a0, uv.y);
                ffma2(acc[(1 * 4 + u) * 2 + 0], a1, uv.x);
                ffma2(acc[(1 * 4 + u) * 2 + 1], a1, uv.y);
            }
        }
#pragma unroll
        for (int ii = 0; ii < 8; ++ii) cur[ii] = nxt[ii];
    }
}

// interleaved fwd+bwd accumulation (double MLP)
__device__ __forceinline__ void accum_pair_direct(
    const float* __restrict__ htf, int tf, const float* Usf, ull* af,
    const float* __restrict__ htb, int tb, const float* Usb, ull* ab,
    int ke, int b2)
{
    const float* basef = htf + (size_t)tf * (ND * NB) + (b2 << 1);
    const float* baseb = htb + (size_t)tb * (ND * NB) + (b2 << 1);
    float2 curf[8], nxtf[8], curb[8], nxtb[8];
#pragma unroll
    for (int ii = 0; ii < 8; ++ii) {
        curf[ii] = *(const float2*)&basef[(size_t)(ii * 8 + ke) * NB];
        curb[ii] = *(const float2*)&baseb[(size_t)(ii * 8 + ke) * NB];
    }
#pragma unroll 1
    for (int c = 0; c < 8; ++c) {
        if (c < 7) {
#pragma unroll
            for (int ii = 0; ii < 8; ++ii) {
                nxtf[ii] = *(const float2*)&basef[(size_t)((c + 1) * 64 + ii * 8 + ke) * NB];
                nxtb[ii] = *(const float2*)&baseb[(size_t)((c + 1) * 64 + ii * 8 + ke) * NB];
            }
        }
#pragma unroll
        for (int ii = 0; ii < 8; ++ii) {
            int k = (c << 6) + ii * 8 + ke;
            const ulonglong2* uf = (const ulonglong2*)&Usf[(size_t)k << 4];
            const ulonglong2* ub = (const ulonglong2*)&Usb[(size_t)k << 4];
            ull a0 = pack2(curf[ii].x, curf[ii].x);
            ull a1 = pack2(curf[ii].y, curf[ii].y);
            ull c0 = pack2(curb[ii].x, curb[ii].x);
            ull c1 = pack2(curb[ii].y, curb[ii].y);
#pragma unroll
            for (int u = 0; u < 4; ++u) {
                ulonglong2 uvf = uf[u];
                ffma2(af[(0 * 4 + u) * 2 + 0], a0, uvf.x);
                ffma2(af[(0 * 4 + u) * 2 + 1], a0, uvf.y);
                ffma2(af[(1 * 4 + u) * 2 + 0], a1, uvf.x);
                ffma2(af[(1 * 4 + u) * 2 + 1], a1, uvf.y);
            }
#pragma unroll
            for (int u = 0; u < 4; ++u) {
                ulonglong2 uvb = ub[u];
                ffma2(ab[(0 * 4 + u) * 2 + 0], c0, uvb.x);
                ffma2(ab[(0 * 4 + u) * 2 + 1], c0, uvb.y);
                ffma2(ab[(1 * 4 + u) * 2 + 0], c1, uvb.x);
                ffma2(ab[(1 * 4 + u) * 2 + 1], c1, uvb.y);
            }
        }
#pragma unroll
        for (int ii = 0; ii < 8; ++ii) { curf[ii] = nxtf[ii]; curb[ii] = nxtb[ii]; }
    }
}

__device__ __forceinline__ void stage_zs(float* zs, const float* __restrict__ xw,
                                         int t, int u0, int tid) {
    int bb = tid >> 2, g = tid & 3;
    float4 xv = *(const float4*)&xw[((size_t)bb * NT + t) * NG + (size_t)g * ND + u0];
    *(float4*)&zs[bb * 20 + (g << 2)] = xv;
}

// store partials; NO internal sync (caller syncs once, possibly for two of these)
__device__ __forceinline__ void scr_store(const ull* acc, float* scr, int ke, int b2) {
    ull* scr_u = (ull*)scr;
#pragma unroll
    for (int bb = 0; bb < 2; ++bb)
#pragma unroll
        for (int u = 0; u < 4; ++u)
#pragma unroll
            for (int p = 0; p < 2; ++p)
                scr_u[(size_t)(((b2 << 1) | bb) * 66 + (ke << 3) + (u << 1) + p)] =
                    acc[(bb * 4 + u) * 2 + p];
}

// reduce + gate math + h_tub store; returns h
__device__ __forceinline__ float gate_reduce(
    float* __restrict__ h_tub, int t, int u0, float& cst,
    const float* zs, const float* scr, int gb, int gu)
{
    float4 z = make_float4(0.f, 0.f, 0.f, 0.f);
#pragma unroll
    for (int k = 0; k < 8; ++k) {
        float4 part = *(const float4*)&scr[gb * 132 + (k << 4) + (gu << 2)];
        z.x += part.x; z.y += part.y; z.z += part.z; z.w += part.w;
    }
    float zi = z.x + zs[gb * 20 + gu];
    float zf = z.y + zs[gb * 20 + 4 + gu];
    float zg = z.z + zs[gb * 20 + 8 + gu];
    float zo = z.w + zs[gb * 20 + 12 + gu];
    cst = fmaf(sigm(zf), cst, sigm(zi) * fmaxf(zg, 0.f));
    float h = sigm(zo) * fmaxf(cst, 0.f);
    h_tub[((size_t)t * ND + u0 + gu) * NB + gb] = h;
    return h;
}

// off-critical-path: shs stage + coalesced h_btu store (caller pre-synced)
__device__ __forceinline__ void gate_post(
    float* __restrict__ h_btu, int t, int u0, float h, float* shs, int tid, int gb, int gu)
{
    shs[(gb << 2) + gu] = h;
    __syncthreads();
    if (tid < 64) {
        float4 h4 = *(const float4*)&shs[tid << 2];
        *(float4*)&h_btu[((size_t)tid * NT + t) * ND + u0] = h4;
    }
}

// smem floats: Us 8192 | zs 1280 | scr 8448 | shs 256 = 18176
#define SMEM_L1 (18176 * 4)

__global__ __launch_bounds__(256) void lstm1_kernel(const float* __restrict__ U)
{
    extern __shared__ float sm[];
    float* Us  = sm;
    float* zs  = sm + 8192;
    float* scr = sm + 9472;
    float* shs = sm + 17920;

    const int tid = threadIdx.x;
    const int ke = tid >> 5, b2 = tid & 31;
    const int gb = tid & 63, gu = tid >> 6;
    const int u0 = blockIdx.x << 2;

    load_U_shared(Us, U, u0, tid);
    stage_zs(zs, g_xw1, 0, u0, tid);
    __syncthreads();

    float cst = 0.f;
    for (int t = 0; t < NT; ++t) {
        ull acc16[16];
#pragma unroll
        for (int i = 0; i < 16; ++i) acc16[i] = 0ull;
        if (t > 0) {
            bar_wait(&g_bar1, (unsigned)t * NCTA);
            accum_direct(g_h1t, t - 1, Us, ke, b2, acc16);
        }
        scr_store(acc16, scr, ke, b2);
        __syncthreads();
        float h = gate_reduce(g_h1t, t, u0, cst, zs, scr, gb, gu);
        if (t < NT - 1) bar_arrive(&g_bar1);      // fence+sync+atomic: h published
        else __syncthreads();
        gate_post(g_h1, t, u0, h, shs, tid, gb, gu);
        if (t + 1 < NT) stage_zs(zs, g_xw1, t + 1, u0, tid);
        __syncthreads();                          // guard scr/zs/shs reuse
    }
}

// smem floats: Ufs 8192 | Ubs 8192 | zsf 1280 | zsb 1280 | scrf 8448 | scrb 8448 | shsf 256 | shsb 256
#define SMEM_FB (36352 * 4)

__global__ __launch_bounds__(256) void lstmfb_kernel(
    const float* __restrict__ Uf, const float* __restrict__ Ub)
{
    extern __shared__ float sm[];
    float* Ufs  = sm;
    float* Ubs  = sm + 8192;
    float* zsf  = sm + 16384;
    float* zsb  = sm + 17664;
    float* scrf = sm + 18944;
    float* scrb = sm + 27392;
    float* shsf = sm + 35840;
    float* shsb = sm + 36096;

    const int tid = threadIdx.x;
    const int ke = tid >> 5, b2 = tid & 31;
    const int gb = tid & 63, gu = tid >> 6;
    const int u0 = blockIdx.x << 2;

    load_U_shared(Ufs, Uf, u0, tid);
    load_U_shared(Ubs, Ub, u0, tid);
    stage_zs(zsf, g_xwf, 0, u0, tid);
    stage_zs(zsb, g_xwb, NT - 1, u0, tid);
    __syncthreads();

    float cf = 0.f, cb = 0.f;
    for (int s = 0; s < NT; ++s) {
        int tf = s, tb = NT - 1 - s;
        ull af[16], ab[16];
#pragma unroll
        for (int i = 0; i < 16; ++i) { af[i] = 0ull; ab[i] = 0ull; }
        if (s > 0) {
            bar_wait(&g_bar2, (unsigned)s * NCTA);
            accum_pair_direct(g_hft, tf - 1, Ufs, af, g_hbt, tb + 1, Ubs, ab, ke, b2);
        }
        scr_store(af, scrf, ke, b2);
        scr_store(ab, scrb, ke, b2);
        __syncthreads();
        float hf = gate_reduce(g_hft, tf, u0, cf, zsf, scrf, gb, gu);
        float hb = gate_reduce(g_hbt, tb, u0, cb, zsb, scrb, gb, gu);
        if (s < NT - 1) bar_arrive(&g_bar2);      // both directions' h published
        else __syncthreads();
        // off-path: shs stages + coalesced h_btu stores for both directions
        shsf[(gb << 2) + gu] = hf;
        shsb[(gb << 2) + gu] = hb;
        __syncthreads();
        if (tid < 64) {
            float4 h4f = *(const float4*)&shsf[tid << 2];
            *(float4*)&g_hf[((size_t)tid * NT + tf) * ND + u0] = h4f;
            float4 h4b = *(const float4*)&shsb[tid << 2];
            *(float4*)&g_hb[((size_t)tid * NT + tb) * ND + u0] = h4b;
        }
        if (s + 1 < NT) {
            stage_zs(zsf, g_xwf, tf + 1, u0, tid);
            stage_zs(zsb, g_xwb, tb - 1, u0, tid);
        }
        __syncthreads();                          // guard scr/zs/shs reuse
    }
}

// ---------------- LayerNorm + residual ----------------
__global__ __launch_bounds__(256) void ln_kernel(
    const float* __restrict__ x, const float* __restrict__ gamma,
    const float* __restrict__ beta, float* __restrict__ out)
{
    __shared__ float red[16];
    __shared__ float s_mu, s_rs;
    const int r = blockIdx.x;
    const int tid = threadIdx.x;

    float4 v;
    if (tid < 128) v = *(const float4*)&g_hf[(size_t)r * ND + (tid << 2)];
    else           v = *(const float4*)&g_hb[(size_t)r * ND + ((tid - 128) << 2)];

    float s = v.x + v.y + v.z + v.w;
    float q = v.x * v.x + v.y * v.y + v.z * v.z + v.w * v.w;
#pragma unroll
    for (int o = 16; o; o >>= 1) {
        s += __shfl_down_sync(0xffffffffu, s, o);
        q += __shfl_down_sync(0xffffffffu, q, o);
    }
    if ((tid & 31) == 0) { red[tid >> 5] = s; red[8 + (tid >> 5)] = q; }
    __syncthreads();
    if (tid == 0) {
        float S = 0.f, Q = 0.f;
#pragma unroll
        for (int i = 0; i < 8; ++i) { S += red[i]; Q += red[8 + i]; }
        float mu = S * (1.f / 1024.f);
        float var = Q * (1.f / 1024.f) - mu * mu;
        s_mu = mu;
        s_rs = rsqrtf(var + 1e-6f);
    }
    __syncthreads();
    float mu = s_mu, rs = s_rs;
    int col = tid << 2;
    float4 g4 = *(const float4*)&gamma[col];
    float4 b4 = *(const float4*)&beta[col];
    float4 xv = *(const float4*)&x[(size_t)r * NI + col];
    float4 o;
    o.x = xv.x + (v.x - mu) * rs * g4.x + b4.x;
    o.y = xv.y + (v.y - mu) * rs * g4.y + b4.y;
    o.z = xv.z + (v.z - mu) * rs * g4.z + b4.z;
    o.w = xv.w + (v.w - mu) * rs * g4.w + b4.w;
    *(float4*)&out[(size_t)r * NI + col] = o;
}

// ---------------- host launch ----------------
// Launch order chosen so lstm1_kernel is launch index 5 (ncu -s 5 -c 1 profiles it).
extern "C" void kernel_launch(void* const* d_in, const int* in_sizes, int n_in,
                              void* d_out, int out_size)
{
    const float* x     = (const float*)d_in[0];
    const float* W1    = (const float*)d_in[1];
    const float* U1    = (const float*)d_in[2];
    const float* b1    = (const float*)d_in[3];
    const float* Wf    = (const float*)d_in[4];
    const float* Uf    = (const float*)d_in[5];
    const float* bf    = (const float*)d_in[6];
    const float* Wb    = (const float*)d_in[7];
    const float* Ub    = (const float*)d_in[8];
    const float* bb    = (const float*)d_in[9];
    const float* gamma = (const float*)d_in[10];
    const float* beta  = (const float*)d_in[11];
    float* out = (float*)d_out;

    void *p_xw1, *p_xwf, *p_xwb, *p_h1, *p_Wt1, *p_Wtf, *p_Wtb;
    void *p_Ah, *p_Al, *p_Bh1, *p_Bl1, *p_Bhf, *p_Blf, *p_Bhb, *p_Blb;
    cudaGetSymbolAddress(&p_xw1, g_xw1);
    cudaGetSymbolAddress(&p_xwf, g_xwf);
    cudaGetSymbolAddress(&p_xwb, g_xwb);
    cudaGetSymbolAddress(&p_h1,  g_h1);
    cudaGetSymbolAddress(&p_Wt1, g_Wt1);
    cudaGetSymbolAddress(&p_Wtf, g_Wtf);
    cudaGetSymbolAddress(&p_Wtb, g_Wtb);
    cudaGetSymbolAddress(&p_Ah,  g_Ah);
    cudaGetSymbolAddress(&p_Al,  g_Al);
    cudaGetSymbolAddress(&p_Bh1, g_Bh1);
    cudaGetSymbolAddress(&p_Bl1, g_Bl1);
    cudaGetSymbolAddress(&p_Bhf, g_Bhf);
    cudaGetSymbolAddress(&p_Blf, g_Blf);
    cudaGetSymbolAddress(&p_Bhb, g_Bhb);
    cudaGetSymbolAddress(&p_Blb, g_Blb);

    cudaFuncSetAttribute(lstm1_kernel,  cudaFuncAttributeMaxDynamicSharedMemorySize, SMEM_L1);
    cudaFuncSetAttribute(lstmfb_kernel, cudaFuncAttributeMaxDynamicSharedMemorySize, SMEM_FB);
    cudaFuncSetAttribute(gemm_fp16_kernel, cudaFuncAttributeMaxDynamicSharedMemorySize, SMEM_GEMM);

    const int M = NB * NT;
    dim3 gg(NG / 128, M / 128);

    // 0..4: minimal dependency chain for gemm1
    reset_bars_kernel<<<1, 1>>>();                                              // 0
    transpose_kernel<<<dim3(NG / 32, NI / 32), 256>>>(W1, (float*)p_Wt1, NI, NG); // 1
    {
        int n4 = NG * NI / 4;
        split_fp16_kernel<<<(n4 + 255) / 256, 256>>>((const float*)p_Wt1, (uint*)p_Bh1, (uint*)p_Bl1, n4); // 2
        n4 = M * NI / 4;
        split_fp16_kernel<<<(n4 + 255) / 256, 256>>>(x, (uint*)p_Ah, (uint*)p_Al, n4);                     // 3
    }
    gemm_fp16_kernel<<<gg, 256, SMEM_GEMM>>>((const uint*)p_Ah, (const uint*)p_Al,
                                             (const uint*)p_Bh1, (const uint*)p_Bl1,
                                             b1, (float*)p_xw1, NI / 2);        // 4
    lstm1_kernel<<<NCTA, 256, SMEM_L1>>>(U1);                                   // 5 <- profiled

    transpose_kernel<<<dim3(NG / 32, ND / 32), 256>>>(Wf, (float*)p_Wtf, ND, NG); // 6
    transpose_kernel<<<dim3(NG / 32, ND / 32), 256>>>(Wb, (float*)p_Wtb, ND, NG); // 7
    {
        int n4 = NG * ND / 4;
        split_fp16_kernel<<<(n4 + 255) / 256, 256>>>((const float*)p_Wtf, (uint*)p_Bhf, (uint*)p_Blf, n4); // 8
        split_fp16_kernel<<<(n4 + 255) / 256, 256>>>((const float*)p_Wtb, (uint*)p_Bhb, (uint*)p_Blb, n4); // 9
        n4 = M * ND / 4;
        split_fp16_kernel<<<(n4 + 255) / 256, 256>>>((const float*)p_h1, (uint*)p_Ah, (uint*)p_Al, n4);    // 10
    }
    gemm_fp16_kernel<<<gg, 256, SMEM_GEMM>>>((const uint*)p_Ah, (const uint*)p_Al,
                                             (const uint*)p_Bhf, (const uint*)p_Blf,
                                             bf, (float*)p_xwf, ND / 2);        // 11
    gemm_fp16_kernel<<<gg, 256, SMEM_GEMM>>>((const uint*)p_Ah, (const uint*)p_Al,
                                             (const uint*)p_Bhb, (const uint*)p_Blb,
                                             bb, (float*)p_xwb, ND / 2);        // 12
    lstmfb_kernel<<<NCTA, 256, SMEM_FB>>>(Uf, Ub);                              // 13
    ln_kernel<<<M, 256>>>(x, gamma, beta, out);                                 // 14
}